// round 10
// baseline (speedup 1.0000x reference)
#include <cuda_runtime.h>
#include <cuda_fp16.h>
#include <cstdint>

// Problem dims (fixed)
#define Tt 4
#define Ll 2048
#define Bb 8
#define Ee 512
#define LB (Ll*Bb)        // 16384
#define Mm (Tt*LB)        // 65536
#define N3 (3*Ee)         // 1536
#define FIX_CAP (1u<<20)
#define DELTA 5e-4f

// Scratch (device globals, allocation-free rule)
static __device__ __half   g_a0  [(size_t)Mm * Ee];   // query hi (fp16)
static __device__ __half   g_a1  [(size_t)Mm * Ee];   // query lo
static __device__ __half   g_w0  [N3 * Ee];           // W_in hi
static __device__ __half   g_w1  [N3 * Ee];           // W_in lo
static __device__ uint8_t  g_spk [(size_t)Mm * N3];   // qkv spikes
static __device__ __half   g_attn[Tt * 64 * 64 * 64]; // attn^T counts (exact fp16)
static __device__ __half   g_s2  [(size_t)Mm * Ee];   // s2 spikes (fp16 0/1)
static __device__ __half   g_whi [Ee * Ee];           // W_out hi
static __device__ __half   g_wlo [Ee * Ee];           // W_out lo
static __device__ unsigned int g_nflag;
static __device__ unsigned int g_list[FIX_CAP];

__device__ __forceinline__ void ldsm_x4(uint32_t& r0, uint32_t& r1,
                                        uint32_t& r2, uint32_t& r3,
                                        const void* p)
{
    uint32_t a = (uint32_t)__cvta_generic_to_shared(p);
    asm volatile("ldmatrix.sync.aligned.m8n8.x4.shared.b16 {%0,%1,%2,%3}, [%4];"
                 : "=r"(r0), "=r"(r1), "=r"(r2), "=r"(r3) : "r"(a));
}

__device__ __forceinline__ void cp16(void* dst, const void* src)
{
    uint32_t d = (uint32_t)__cvta_generic_to_shared(dst);
    asm volatile("cp.async.cg.shared.global [%0], [%1], 16;" :: "r"(d), "l"(src));
}
#define CP_COMMIT() asm volatile("cp.async.commit_group;")
#define CP_WAIT1()  asm volatile("cp.async.wait_group 1;")
#define CP_WAIT0()  asm volatile("cp.async.wait_group 0;")

#define MMA_F16(acc, a0, a1, a2, a3, b0, b1)                                \
    asm volatile(                                                           \
        "mma.sync.aligned.m16n8k16.row.col.f32.f16.f16.f32 "                \
        "{%0,%1,%2,%3}, {%4,%5,%6,%7}, {%8,%9}, {%0,%1,%2,%3};"             \
        : "+f"(acc[0]), "+f"(acc[1]), "+f"(acc[2]), "+f"(acc[3])            \
        : "r"(a0), "r"(a1), "r"(a2), "r"(a3), "r"(b0), "r"(b1))

// gemm stage stride: 128 rows x 40 halves
#define STG 5120
// kv transpose tile stride (halves): 272 bytes, 16B-aligned rows for ldmatrix
#define KVS 136
// spike (0/1) -> fp16 bit pattern
#define H1(u) ((unsigned short)((u) * 0x3C00u))

// ---------------------------------------------------------------------------
// fp16 hi/lo split helpers
// ---------------------------------------------------------------------------
__global__ __launch_bounds__(256) void split_kernel(
    const float* __restrict__ src, __half* __restrict__ d0,
    __half* __restrict__ d1)
{
    size_t i4 = ((size_t)blockIdx.x * 256 + threadIdx.x) * 4;
    float4 v = *(const float4*)(src + i4);
    float x[4] = {v.x, v.y, v.z, v.w};
    __half h[4], l[4];
    #pragma unroll
    for (int j = 0; j < 4; j++) {
        h[j] = __float2half_rn(x[j]);
        l[j] = __float2half_rn(x[j] - __half2float(h[j]));
    }
    *(uint2*)(d0 + i4) = *(uint2*)h;
    *(uint2*)(d1 + i4) = *(uint2*)l;
}

__global__ void zero_flag_kernel() { g_nflag = 0u; }

// ---------------------------------------------------------------------------
// Fused GEMM1 + LIF + flag. Grid (12 n-tiles, 128 lb-tiles); t loops inside
// the CTA. fp16 2-split, 3 mma passes, ldmatrix, cp.async pipeline flattened
// over (t, k0). Membrane state in SMEM (thread-exclusive). Values computed
// are bit-identical to the unfused R9 path (no g_proj round-trip).
// ---------------------------------------------------------------------------
__global__ __launch_bounds__(256) void gemm1_lif_kernel(
    const float* __restrict__ bias)
{
    extern __shared__ __half dsm[];
    __half* A0s = dsm;              // [2][128][40]
    __half* A1s = dsm + 2*STG;
    __half* B0s = dsm + 4*STG;
    __half* B1s = dsm + 6*STG;
    float*  vsm = (float*)(dsm + 8*STG);   // [128][128] membrane potentials

    const int bn = blockIdx.x * 128;   // f tile
    const int bm = blockIdx.y * 128;   // lb tile
    const int tid  = threadIdx.x;
    const int wid  = tid >> 5;
    const int lane = tid & 31;
    const int wm = wid >> 1;
    const int wn = wid & 1;
    const int lr = lane >> 2;
    const int lc = (lane & 3) * 2;

    const int a_r = lane & 15, a_k = (lane >> 4) * 8;
    const int b_r = (lane & 7) + ((lane >> 4) << 3);
    const int b_k = ((lane >> 3) & 1) * 8;

    // bias cache for this thread's 16 columns
    float bc[8][2];
    #pragma unroll
    for (int ni = 0; ni < 8; ni++) {
        int col = bn + wn*64 + ni*8 + lc;
        bc[ni][0] = bias[col];
        bc[ni][1] = bias[col + 1];
    }

    // init membrane state (thread-exclusive entries; no sync needed)
    #pragma unroll
    for (int mi = 0; mi < 2; mi++)
        #pragma unroll
        for (int ni = 0; ni < 8; ni++)
            #pragma unroll
            for (int r = 0; r < 4; r++) {
                int row = wm*32 + mi*16 + lr + (r >> 1)*8;
                int col = wn*64 + ni*8 + lc + (r & 1);
                vsm[row*128 + col] = 0.f;
            }

    uint32_t fm[2] = {0u, 0u};   // flag bits: fm[mi] bit (ni*4+r)

    // stage loader for flattened iteration it = t*16 + k-tile
    auto load_stage = [&](int s, int it) {
        int t  = it >> 4;
        int k0 = (it & 15) * 32;
        #pragma unroll
        for (int i = tid; i < 512; i += 256) {
            int row = i >> 2, c8 = (i & 3) << 3;
            int so = s*STG + row*40 + c8;
            size_t offa = ((size_t)t * LB + bm + row) * Ee + k0 + c8;
            cp16(A0s + so, g_a0 + offa);
            cp16(A1s + so, g_a1 + offa);
            size_t offb = (size_t)(bn + row) * Ee + k0 + c8;
            cp16(B0s + so, g_w0 + offb);
            cp16(B1s + so, g_w1 + offb);
        }
    };

    load_stage(0, 0);
    CP_COMMIT();

    float acc[2][8][4];
    const int NIT = Tt * 16;   // 64
    for (int it = 0; it < NIT; it++) {
        if (it + 1 < NIT) {
            load_stage((it + 1) & 1, it + 1);
            CP_COMMIT();
            CP_WAIT1();
        } else {
            CP_WAIT0();
        }
        __syncthreads();

        if ((it & 15) == 0) {
            #pragma unroll
            for (int mi = 0; mi < 2; mi++)
                #pragma unroll
                for (int ni = 0; ni < 8; ni++)
                    #pragma unroll
                    for (int r = 0; r < 4; r++) acc[mi][ni][r] = 0.f;
        }

        const int sb = (it & 1) * STG;
        #pragma unroll
        for (int kk = 0; kk < 32; kk += 16) {
            uint32_t a0[2][4], a1[2][4];
            #pragma unroll
            for (int mi = 0; mi < 2; mi++) {
                int rb = wm*32 + mi*16;
                ldsm_x4(a0[mi][0], a0[mi][1], a0[mi][2], a0[mi][3],
                        A0s + sb + (rb + a_r)*40 + kk + a_k);
                ldsm_x4(a1[mi][0], a1[mi][1], a1[mi][2], a1[mi][3],
                        A1s + sb + (rb + a_r)*40 + kk + a_k);
            }
            uint32_t bh[8][2], bl[8][2];
            #pragma unroll
            for (int nb = 0; nb < 4; nb++) {
                int n0 = wn*64 + nb*16;
                ldsm_x4(bh[nb*2][0], bh[nb*2][1], bh[nb*2+1][0], bh[nb*2+1][1],
                        B0s + sb + (n0 + b_r)*40 + kk + b_k);
                ldsm_x4(bl[nb*2][0], bl[nb*2][1], bl[nb*2+1][0], bl[nb*2+1][1],
                        B1s + sb + (n0 + b_r)*40 + kk + b_k);
            }
            #pragma unroll
            for (int ni = 0; ni < 8; ni++) {
                #pragma unroll
                for (int mi = 0; mi < 2; mi++) {
                    MMA_F16(acc[mi][ni], a0[mi][0], a0[mi][1], a0[mi][2],
                            a0[mi][3], bh[ni][0], bh[ni][1]);
                    MMA_F16(acc[mi][ni], a1[mi][0], a1[mi][1], a1[mi][2],
                            a1[mi][3], bh[ni][0], bh[ni][1]);
                    MMA_F16(acc[mi][ni], a0[mi][0], a0[mi][1], a0[mi][2],
                            a0[mi][3], bl[ni][0], bl[ni][1]);
                }
            }
        }

        if ((it & 15) == 15) {
            // Epilogue for timestep t: bias + LIF(1.0), flag marginal,
            // write uint8 spikes. (Logic validated bit-exact in R5.)
            const int t = it >> 4;
            #pragma unroll
            for (int mi = 0; mi < 2; mi++) {
                #pragma unroll
                for (int ni = 0; ni < 8; ni++) {
                    int colb = bn + wn*64 + ni*8 + lc;
                    #pragma unroll
                    for (int rp = 0; rp < 2; rp++) {
                        int rowl = wm*32 + mi*16 + lr + rp*8;
                        uint8_t sp[2];
                        #pragma unroll
                        for (int c = 0; c < 2; c++) {
                            int r = rp*2 + c;
                            float x = acc[mi][ni][r] + bc[ni][c];
                            float* vp = vsm + rowl*128 + wn*64 + ni*8 + lc + c;
                            float v = *vp;
                            float h = v + (x - v) * 0.5f;
                            if (fabsf(h - 1.0f) < DELTA)
                                fm[mi] |= (1u << (ni*4 + r));
                            bool s = (h - 1.0f) >= 0.f;
                            sp[c] = s ? 1 : 0;
                            *vp = s ? 0.f : h;
                        }
                        uchar2 u = {sp[0], sp[1]};
                        *(uchar2*)(g_spk + (size_t)t * LB * N3
                                   + (size_t)(bm + rowl) * N3 + colb) = u;
                    }
                }
            }
        }
        __syncthreads();
    }

    // push flagged neurons (index = lb*N3 + f)
    #pragma unroll
    for (int mi = 0; mi < 2; mi++) {
        if (fm[mi] == 0u) continue;
        #pragma unroll
        for (int ni = 0; ni < 8; ni++) {
            #pragma unroll
            for (int r = 0; r < 4; r++) {
                if (fm[mi] & (1u << (ni*4 + r))) {
                    int row = bm + wm*32 + mi*16 + lr + (r >> 1)*8;
                    int col = bn + wn*64 + ni*8 + lc + (r & 1);
                    unsigned int p = atomicAdd(&g_nflag, 1u);
                    if (p < FIX_CAP)
                        g_list[p] = (unsigned int)((size_t)row * N3 + col);
                }
            }
        }
    }
}

// ---------------------------------------------------------------------------
// Exact fixup: sequential-K fp32 FMA (bitwise-reference order).
// ---------------------------------------------------------------------------
__global__ __launch_bounds__(256) void fixup_kernel(
    const float* __restrict__ Q, const float* __restrict__ W,
    const float* __restrict__ bias)
{
    unsigned int tid = blockIdx.x * 256 + threadIdx.x;
    unsigned int n = g_nflag; if (n > FIX_CAP) n = FIX_CAP;
    if (tid >= n) return;
    unsigned int i = g_list[tid];
    int lb = i / N3;
    int f  = i - lb * N3;

    const float* wr = W + (size_t)f * Ee;
    float acc[4] = {0.f, 0.f, 0.f, 0.f};
    for (int k = 0; k < Ee; k += 4) {
        float4 wv = *(const float4*)(wr + k);
        #pragma unroll
        for (int t = 0; t < Tt; t++) {
            const float* qr = Q + ((size_t)t * LB + lb) * Ee + k;
            float4 qv = *(const float4*)qr;
            acc[t] = fmaf(qv.x, wv.x, acc[t]);
            acc[t] = fmaf(qv.y, wv.y, acc[t]);
            acc[t] = fmaf(qv.z, wv.z, acc[t]);
            acc[t] = fmaf(qv.w, wv.w, acc[t]);
        }
    }
    float b = bias[f];
    float v = 0.f;
    #pragma unroll
    for (int t = 0; t < Tt; t++) {
        float x = acc[t] + b;
        float h = v + (x - v) * 0.5f;
        bool s = (h - 1.0f) >= 0.f;
        g_spk[(size_t)t * LB * N3 + i] = s ? 1 : 0;
        v = s ? 0.f : h;
    }
}

// ---------------------------------------------------------------------------
// kv attention on tensor cores: attnT[t,n][e][d] = sum_l v[l,e] * k[l,d].
// (Validated R9: exact integer counts, no atomics.)
// ---------------------------------------------------------------------------
__global__ __launch_bounds__(256) void kv_attn_kernel()
{
    const int n = blockIdx.x, t = blockIdx.y;
    const int b = n >> 3, h = n & 7;
    __shared__ __half vT[64 * KVS];   // [e][l]
    __shared__ __half kT[64 * KVS];   // [d][l]

    const int tid  = threadIdx.x;
    const int wid  = tid >> 5;
    const int lane = tid & 31;
    const int e0 = (wid >> 1) * 16;
    const int d0 = (wid & 1) * 32;
    const int lr = lane >> 2;
    const int lc = (lane & 3) * 2;

    const int a_r = lane & 15, a_k = (lane >> 4) * 8;
    const int b_r = (lane & 7) + ((lane >> 4) << 3);
    const int b_k = ((lane >> 3) & 1) * 8;

    float acc[4][4];
    #pragma unroll
    for (int ni = 0; ni < 4; ni++)
        #pragma unroll
        for (int r = 0; r < 4; r++) acc[ni][r] = 0.f;

    for (int l0 = 0; l0 < Ll; l0 += 128) {
        __syncthreads();
        for (int i = tid; i < 2048; i += 256) {
            int ll = i >> 4, d4 = (i & 15) << 2;
            size_t base = ((size_t)t * LB + (size_t)(l0 + ll) * Bb + b) * N3
                          + h * 64 + d4;
            uchar4 kc = *(const uchar4*)(g_spk + base + 512);
            uchar4 vc = *(const uchar4*)(g_spk + base + 1024);
            kT[(d4+0)*KVS + ll] = __ushort_as_half(H1(kc.x));
            kT[(d4+1)*KVS + ll] = __ushort_as_half(H1(kc.y));
            kT[(d4+2)*KVS + ll] = __ushort_as_half(H1(kc.z));
            kT[(d4+3)*KVS + ll] = __ushort_as_half(H1(kc.w));
            vT[(d4+0)*KVS + ll] = __ushort_as_half(H1(vc.x));
            vT[(d4+1)*KVS + ll] = __ushort_as_half(H1(vc.y));
            vT[(d4+2)*KVS + ll] = __ushort_as_half(H1(vc.z));
            vT[(d4+3)*KVS + ll] = __ushort_as_half(H1(vc.w));
        }
        __syncthreads();

        #pragma unroll
        for (int kk = 0; kk < 128; kk += 16) {
            uint32_t a[4];
            ldsm_x4(a[0], a[1], a[2], a[3], &vT[(e0 + a_r)*KVS + kk + a_k]);
            uint32_t bt[4][2];
            #pragma unroll
            for (int nb = 0; nb < 2; nb++)
                ldsm_x4(bt[nb*2][0], bt[nb*2][1], bt[nb*2+1][0], bt[nb*2+1][1],
                        &kT[(d0 + nb*16 + b_r)*KVS + kk + b_k]);
            #pragma unroll
            for (int ni = 0; ni < 4; ni++)
                MMA_F16(acc[ni], a[0], a[1], a[2], a[3], bt[ni][0], bt[ni][1]);
        }
    }

    __half* ap = g_attn + (size_t)(t * 64 + n) * 4096;
    #pragma unroll
    for (int ni = 0; ni < 4; ni++) {
        int d = d0 + ni*8 + lc;
        *(__half2*)(ap + (e0 + lr) * 64 + d) =
            __floats2half2_rn(acc[ni][0], acc[ni][1]);
        *(__half2*)(ap + (e0 + lr + 8) * 64 + d) =
            __floats2half2_rn(acc[ni][2], acc[ni][3]);
    }
}

// ---------------------------------------------------------------------------
// q @ attn on tensor cores + fused LIF(0.5). (Validated R9: exact.)
// ---------------------------------------------------------------------------
__global__ __launch_bounds__(256) void qattn_lif_kernel()
{
    const int n = blockIdx.y, lt = blockIdx.x;
    const int b = n >> 3, h = n & 7;
    __shared__ __half qs[128][72];
    __shared__ __half at[64][72];

    const int tid  = threadIdx.x;
    const int wid  = tid >> 5;
    const int lane = tid & 31;
    const int wm = wid >> 1;
    const int wn = wid & 1;
    const int lr = lane >> 2;
    const int lc = (lane & 3) * 2;

    const int a_r = lane & 15, a_k = (lane >> 4) * 8;
    const int b_r = (lane & 7) + ((lane >> 4) << 3);
    const int b_k = ((lane >> 3) & 1) * 8;

    float vmem[2][4][4];
    #pragma unroll
    for (int mi = 0; mi < 2; mi++)
        #pragma unroll
        for (int ni = 0; ni < 4; ni++)
            #pragma unroll
            for (int r = 0; r < 4; r++) vmem[mi][ni][r] = 0.f;

    for (int t = 0; t < Tt; t++) {
        __syncthreads();
        for (int i = tid; i < 2048; i += 256) {
            int ll = i >> 4, d4 = (i & 15) << 2;
            size_t base = ((size_t)t * LB + (size_t)(lt*128 + ll) * Bb + b) * N3
                          + h * 64 + d4;
            uchar4 qc = *(const uchar4*)(g_spk + base);
            unsigned short hh[4] = {H1(qc.x), H1(qc.y), H1(qc.z), H1(qc.w)};
            *(uint2*)&qs[ll][d4] = *(uint2*)hh;
        }
        for (int i = tid; i < 512; i += 256) {
            int row = i >> 3, c8 = (i & 7) << 3;
            *(uint4*)&at[row][c8] =
                *(const uint4*)(g_attn + (size_t)(t*64 + n) * 4096 + row*64 + c8);
        }
        __syncthreads();

        float acc[2][4][4];
        #pragma unroll
        for (int mi = 0; mi < 2; mi++)
            #pragma unroll
            for (int ni = 0; ni < 4; ni++)
                #pragma unroll
                for (int r = 0; r < 4; r++) acc[mi][ni][r] = 0.f;

        #pragma unroll
        for (int kk = 0; kk < 64; kk += 16) {
            uint32_t a[2][4];
            #pragma unroll
            for (int mi = 0; mi < 2; mi++)
                ldsm_x4(a[mi][0], a[mi][1], a[mi][2], a[mi][3],
                        &qs[wm*32 + mi*16 + a_r][kk + a_k]);
            uint32_t bt[4][2];
            #pragma unroll
            for (int nb = 0; nb < 2; nb++)
                ldsm_x4(bt[nb*2][0], bt[nb*2][1], bt[nb*2+1][0], bt[nb*2+1][1],
                        &at[wn*32 + nb*16 + b_r][kk + b_k]);
            #pragma unroll
            for (int ni = 0; ni < 4; ni++)
                #pragma unroll
                for (int mi = 0; mi < 2; mi++)
                    MMA_F16(acc[mi][ni], a[mi][0], a[mi][1], a[mi][2], a[mi][3],
                            bt[ni][0], bt[ni][1]);
        }

        #pragma unroll
        for (int mi = 0; mi < 2; mi++) {
            #pragma unroll
            for (int ni = 0; ni < 4; ni++) {
                int e = wn*32 + ni*8 + lc;
                #pragma unroll
                for (int rp = 0; rp < 2; rp++) {
                    int l = lt*128 + wm*32 + mi*16 + lr + rp*8;
                    unsigned short sp[2];
                    #pragma unroll
                    for (int c = 0; c < 2; c++) {
                        int r = rp*2 + c;
                        float x = acc[mi][ni][r] * 0.125f;
                        float v = vmem[mi][ni][r];
                        float hh = v + (x - v) * 0.5f;
                        bool s = (hh - 0.5f) >= 0.f;
                        sp[c] = s ? 0x3C00 : 0;
                        vmem[mi][ni][r] = s ? 0.f : hh;
                    }
                    *(uint32_t*)(g_s2 + (((size_t)t * Ll + l) * Bb + b) * Ee
                                 + h * 64 + e) = *(uint32_t*)sp;
                }
            }
        }
    }
}

// ---------------------------------------------------------------------------
// Split W_out into fp16 hi + lo
// ---------------------------------------------------------------------------
__global__ __launch_bounds__(256) void wsplit_kernel(const float* __restrict__ W)
{
    int i = blockIdx.x * 256 + threadIdx.x;
    float w = W[i];
    __half hi = __float2half_rn(w);
    g_whi[i] = hi;
    g_wlo[i] = __float2half_rn(w - __half2float(hi));
}

// ---------------------------------------------------------------------------
// GEMM5: out = s2 @ (Whi + Wlo)^T + bias, fp16 split, ldmatrix + cp.async.
// ---------------------------------------------------------------------------
__global__ __launch_bounds__(256) void gemm5_mma_kernel(
    const float* __restrict__ bias, float* __restrict__ C)
{
    extern __shared__ __half dsm[];
    __half* As  = dsm;              // [2][128][40]
    __half* Bhi = dsm + 2*STG;
    __half* Blo = dsm + 4*STG;

    const int bm = blockIdx.y * 128;
    const int bn = blockIdx.x * 128;
    const int tid  = threadIdx.x;
    const int wid  = tid >> 5;
    const int lane = tid & 31;
    const int wm = wid >> 1;
    const int wn = wid & 1;
    const int lr = lane >> 2;
    const int lc = (lane & 3) * 2;

    const int a_r = lane & 15, a_k = (lane >> 4) * 8;
    const int b_r = (lane & 7) + ((lane >> 4) << 3);
    const int b_k = ((lane >> 3) & 1) * 8;

    float acc[2][8][4];
    #pragma unroll
    for (int mi = 0; mi < 2; mi++)
        #pragma unroll
        for (int ni = 0; ni < 8; ni++)
            #pragma unroll
            for (int r = 0; r < 4; r++) acc[mi][ni][r] = 0.f;

    auto load_stage = [&](int s, int k0) {
        #pragma unroll
        for (int i = tid; i < 512; i += 256) {
            int row = i >> 2, c8 = (i & 3) << 3;
            int so = s*STG + row*40 + c8;
            cp16(As + so, g_s2 + (size_t)(bm + row) * Ee + k0 + c8);
            size_t off = (size_t)(bn + row) * Ee + k0 + c8;
            cp16(Bhi + so, g_whi + off);
            cp16(Blo + so, g_wlo + off);
        }
    };

    load_stage(0, 0);
    CP_COMMIT();

    const int NT = Ee / 32;
    for (int it = 0; it < NT; it++) {
        if (it + 1 < NT) {
            load_stage((it + 1) & 1, (it + 1) * 32);
            CP_COMMIT();
            CP_WAIT1();
        } else {
            CP_WAIT0();
        }
        __syncthreads();

        const int sb = (it & 1) * STG;
        #pragma unroll
        for (int kk = 0; kk < 32; kk += 16) {
            uint32_t a[2][4];
            #pragma unroll
            for (int mi = 0; mi < 2; mi++) {
                int rb = wm*32 + mi*16;
                ldsm_x4(a[mi][0], a[mi][1], a[mi][2], a[mi][3],
                        As + sb + (rb + a_r)*40 + kk + a_k);
            }
            uint32_t bh[8][2], bl[8][2];
            #pragma unroll
            for (int nb = 0; nb < 4; nb++) {
                int n0 = wn*64 + nb*16;
                ldsm_x4(bh[nb*2][0], bh[nb*2][1], bh[nb*2+1][0], bh[nb*2+1][1],
                        Bhi + sb + (n0 + b_r)*40 + kk + b_k);
                ldsm_x4(bl[nb*2][0], bl[nb*2][1], bl[nb*2+1][0], bl[nb*2+1][1],
                        Blo + sb + (n0 + b_r)*40 + kk + b_k);
            }
            #pragma unroll
            for (int ni = 0; ni < 8; ni++) {
                #pragma unroll
                for (int mi = 0; mi < 2; mi++) {
                    MMA_F16(acc[mi][ni], a[mi][0], a[mi][1], a[mi][2], a[mi][3],
                            bh[ni][0], bh[ni][1]);
                    MMA_F16(acc[mi][ni], a[mi][0], a[mi][1], a[mi][2], a[mi][3],
                            bl[ni][0], bl[ni][1]);
                }
            }
        }
        __syncthreads();
    }

    #pragma unroll
    for (int mi = 0; mi < 2; mi++) {
        #pragma unroll
        for (int ni = 0; ni < 8; ni++) {
            int col = bn + wn*64 + ni*8 + lc;
            float b0 = bias[col], b1 = bias[col + 1];
            int row0 = bm + wm*32 + mi*16 + lr;
            *(float2*)(C + (size_t)row0 * Ee + col) =
                make_float2(acc[mi][ni][0] + b0, acc[mi][ni][1] + b1);
            *(float2*)(C + (size_t)(row0 + 8) * Ee + col) =
                make_float2(acc[mi][ni][2] + b0, acc[mi][ni][3] + b1);
        }
    }
}

// ---------------------------------------------------------------------------
extern "C" void kernel_launch(void* const* d_in, const int* in_sizes, int n_in,
                              void* d_out, int out_size)
{
    const float* query = (const float*)d_in[0];   // (T,L,B,E)
    const float* w_in  = (const float*)d_in[1];   // (3E, E)
    const float* b_in  = (const float*)d_in[2];   // (3E)
    const float* w_out = (const float*)d_in[3];   // (E, E)
    const float* b_out = (const float*)d_in[4];   // (E)
    float* out = (float*)d_out;                   // (T,L,B,E)

    void *p_a0, *p_a1, *p_w0, *p_w1;
    cudaGetSymbolAddress(&p_a0, g_a0);
    cudaGetSymbolAddress(&p_a1, g_a1);
    cudaGetSymbolAddress(&p_w0, g_w0);
    cudaGetSymbolAddress(&p_w1, g_w1);

    // 0) zero flag counter + fp16 splits
    zero_flag_kernel<<<1, 1>>>();
    split_kernel<<<((size_t)Mm * Ee / 4) / 256, 256>>>(
        query, (__half*)p_a0, (__half*)p_a1);
    split_kernel<<<((size_t)N3 * Ee / 4) / 256, 256>>>(
        w_in, (__half*)p_w0, (__half*)p_w1);
    wsplit_kernel<<<(Ee * Ee) / 256, 256>>>(w_out);

    // 1) fused proj + LIF + flag on tensor cores (no g_proj round-trip)
    const int SM1 = 8 * STG * (int)sizeof(__half) + 128 * 128 * 4;  // 144 KB
    cudaFuncSetAttribute(gemm1_lif_kernel,
                         cudaFuncAttributeMaxDynamicSharedMemorySize, SM1);
    gemm1_lif_kernel<<<dim3(N3 / 128, LB / 128), 256, SM1>>>(b_in);

    // 2) exact fixup of flagged neurons
    fixup_kernel<<<FIX_CAP / 256, 256>>>(query, w_in, b_in);

    // 3) attnT = v^T k per (t, head) on tensor cores
    kv_attn_kernel<<<dim3(64, Tt), 256>>>();

    // 4) out = q @ attn * 0.125 -> LIF(0.5) -> s2 spikes, tensor cores
    qattn_lif_kernel<<<dim3(Ll / 128, 64), 256>>>();

    // 5) final = s2 @ W_out^T + b_out on tensor cores
    const int SM5 = 6 * STG * (int)sizeof(__half);   // 60 KB
    cudaFuncSetAttribute(gemm5_mma_kernel,
                         cudaFuncAttributeMaxDynamicSharedMemorySize, SM5);
    gemm5_mma_kernel<<<dim3(Ee / 128, Mm / 128), 256, SM5>>>(b_out, out);
}

// round 11
// speedup vs baseline: 1.1787x; 1.1787x over previous
#include <cuda_runtime.h>
#include <cuda_fp16.h>
#include <cstdint>

// Problem dims (fixed)
#define Tt 4
#define Ll 2048
#define Bb 8
#define Ee 512
#define LB (Ll*Bb)        // 16384
#define Mm (Tt*LB)        // 65536
#define N3 (3*Ee)         // 1536
#define FIX_CAP (1u<<20)
#define DELTA 2.5e-3f

// Scratch (device globals, allocation-free rule)
static __device__ float    g_proj[(size_t)Mm * N3];   // fast proj
static __device__ __half   g_a0  [(size_t)Mm * Ee];   // query hi (fp16)
static __device__ __half   g_a1  [(size_t)Mm * Ee];   // query lo
static __device__ __half   g_w0  [N3 * Ee];           // W_in hi
static __device__ uint8_t  g_spk [(size_t)Mm * N3];   // qkv spikes
static __device__ __half   g_attn[Tt * 64 * 64 * 64]; // attn^T counts (exact fp16)
static __device__ __half   g_s2  [(size_t)Mm * Ee];   // s2 spikes (fp16 0/1)
static __device__ __half   g_whi [Ee * Ee];           // W_out hi
static __device__ __half   g_wlo [Ee * Ee];           // W_out lo
static __device__ unsigned int g_nflag;
static __device__ unsigned int g_list[FIX_CAP];

__device__ __forceinline__ void ldsm_x4(uint32_t& r0, uint32_t& r1,
                                        uint32_t& r2, uint32_t& r3,
                                        const void* p)
{
    uint32_t a = (uint32_t)__cvta_generic_to_shared(p);
    asm volatile("ldmatrix.sync.aligned.m8n8.x4.shared.b16 {%0,%1,%2,%3}, [%4];"
                 : "=r"(r0), "=r"(r1), "=r"(r2), "=r"(r3) : "r"(a));
}

__device__ __forceinline__ void cp16(void* dst, const void* src)
{
    uint32_t d = (uint32_t)__cvta_generic_to_shared(dst);
    asm volatile("cp.async.cg.shared.global [%0], [%1], 16;" :: "r"(d), "l"(src));
}
#define CP_COMMIT() asm volatile("cp.async.commit_group;")
#define CP_WAIT1()  asm volatile("cp.async.wait_group 1;")
#define CP_WAIT0()  asm volatile("cp.async.wait_group 0;")

#define MMA_F16(acc, a0, a1, a2, a3, b0, b1)                                \
    asm volatile(                                                           \
        "mma.sync.aligned.m16n8k16.row.col.f32.f16.f16.f32 "                \
        "{%0,%1,%2,%3}, {%4,%5,%6,%7}, {%8,%9}, {%0,%1,%2,%3};"             \
        : "+f"(acc[0]), "+f"(acc[1]), "+f"(acc[2]), "+f"(acc[3])            \
        : "r"(a0), "r"(a1), "r"(a2), "r"(a3), "r"(b0), "r"(b1))

// gemm stage stride: 128 rows x 40 halves
#define STG 5120
// kv transpose tile stride (halves): 272 bytes, 16B-aligned rows for ldmatrix
#define KVS 136
// spike (0/1) -> fp16 bit pattern
#define H1(u) ((unsigned short)((u) * 0x3C00u))

// ---------------------------------------------------------------------------
// fp16 hi/lo split (query) and hi-only convert (W_in)
// ---------------------------------------------------------------------------
__global__ __launch_bounds__(256) void split_kernel(
    const float* __restrict__ src, __half* __restrict__ d0,
    __half* __restrict__ d1)
{
    size_t i4 = ((size_t)blockIdx.x * 256 + threadIdx.x) * 4;
    float4 v = *(const float4*)(src + i4);
    float x[4] = {v.x, v.y, v.z, v.w};
    __half h[4], l[4];
    #pragma unroll
    for (int j = 0; j < 4; j++) {
        h[j] = __float2half_rn(x[j]);
        l[j] = __float2half_rn(x[j] - __half2float(h[j]));
    }
    *(uint2*)(d0 + i4) = *(uint2*)h;
    *(uint2*)(d1 + i4) = *(uint2*)l;
}

__global__ __launch_bounds__(256) void conv_kernel(
    const float* __restrict__ src, __half* __restrict__ d0)
{
    size_t i4 = ((size_t)blockIdx.x * 256 + threadIdx.x) * 4;
    float4 v = *(const float4*)(src + i4);
    __half h[4] = {__float2half_rn(v.x), __float2half_rn(v.y),
                   __float2half_rn(v.z), __float2half_rn(v.w)};
    *(uint2*)(d0 + i4) = *(uint2*)h;
}

__global__ void zero_flag_kernel() { g_nflag = 0u; }

// ---------------------------------------------------------------------------
// GEMM1 fast path: proj = q @ W_in^T + bias, 2-pass fp16 split (a0w0 + a1w0;
// dropped a*w1 rms ~2.8e-4, repaired by exact fixup). ldmatrix + cp.async
// 2-stage pipeline. Block 128x128, 8 warps (4m x 2n).
// ---------------------------------------------------------------------------
__global__ __launch_bounds__(256) void gemm1_fast_kernel(
    const float* __restrict__ bias)
{
    extern __shared__ __half dsm[];
    __half* A0s = dsm;              // [2][128][40]
    __half* A1s = dsm + 2*STG;
    __half* B0s = dsm + 4*STG;

    const int bm = blockIdx.y * 128;
    const int bn = blockIdx.x * 128;
    const int tid  = threadIdx.x;
    const int wid  = tid >> 5;
    const int lane = tid & 31;
    const int wm = wid >> 1;
    const int wn = wid & 1;
    const int lr = lane >> 2;
    const int lc = (lane & 3) * 2;

    const int a_r = lane & 15, a_k = (lane >> 4) * 8;
    const int b_r = (lane & 7) + ((lane >> 4) << 3);
    const int b_k = ((lane >> 3) & 1) * 8;

    float acc[2][8][4];
    #pragma unroll
    for (int mi = 0; mi < 2; mi++)
        #pragma unroll
        for (int ni = 0; ni < 8; ni++)
            #pragma unroll
            for (int r = 0; r < 4; r++) acc[mi][ni][r] = 0.f;

    auto load_stage = [&](int s, int k0) {
        #pragma unroll
        for (int i = tid; i < 512; i += 256) {
            int row = i >> 2, c8 = (i & 3) << 3;
            int so = s*STG + row*40 + c8;
            size_t offa = (size_t)(bm + row) * Ee + k0 + c8;
            cp16(A0s + so, g_a0 + offa);
            cp16(A1s + so, g_a1 + offa);
            cp16(B0s + so, g_w0 + (size_t)(bn + row) * Ee + k0 + c8);
        }
    };

    load_stage(0, 0);
    CP_COMMIT();

    const int NT = Ee / 32;   // 16
    for (int it = 0; it < NT; it++) {
        if (it + 1 < NT) {
            load_stage((it + 1) & 1, (it + 1) * 32);
            CP_COMMIT();
            CP_WAIT1();
        } else {
            CP_WAIT0();
        }
        __syncthreads();

        const int sb = (it & 1) * STG;
        #pragma unroll
        for (int kk = 0; kk < 32; kk += 16) {
            uint32_t a0[2][4], a1[2][4];
            #pragma unroll
            for (int mi = 0; mi < 2; mi++) {
                int rb = wm*32 + mi*16;
                ldsm_x4(a0[mi][0], a0[mi][1], a0[mi][2], a0[mi][3],
                        A0s + sb + (rb + a_r)*40 + kk + a_k);
                ldsm_x4(a1[mi][0], a1[mi][1], a1[mi][2], a1[mi][3],
                        A1s + sb + (rb + a_r)*40 + kk + a_k);
            }
            uint32_t bh[8][2];
            #pragma unroll
            for (int nb = 0; nb < 4; nb++) {
                int n0 = wn*64 + nb*16;
                ldsm_x4(bh[nb*2][0], bh[nb*2][1], bh[nb*2+1][0], bh[nb*2+1][1],
                        B0s + sb + (n0 + b_r)*40 + kk + b_k);
            }
            #pragma unroll
            for (int ni = 0; ni < 8; ni++) {
                #pragma unroll
                for (int mi = 0; mi < 2; mi++) {
                    MMA_F16(acc[mi][ni], a0[mi][0], a0[mi][1], a0[mi][2],
                            a0[mi][3], bh[ni][0], bh[ni][1]);
                    MMA_F16(acc[mi][ni], a1[mi][0], a1[mi][1], a1[mi][2],
                            a1[mi][3], bh[ni][0], bh[ni][1]);
                }
            }
        }
        __syncthreads();
    }

    #pragma unroll
    for (int mi = 0; mi < 2; mi++) {
        #pragma unroll
        for (int ni = 0; ni < 8; ni++) {
            int col = bn + wn*64 + ni*8 + lc;
            float b0 = bias[col], b1 = bias[col + 1];
            int row0 = bm + wm*32 + mi*16 + lr;
            *(float2*)(g_proj + (size_t)row0 * N3 + col) =
                make_float2(acc[mi][ni][0] + b0, acc[mi][ni][1] + b1);
            *(float2*)(g_proj + (size_t)(row0 + 8) * N3 + col) =
                make_float2(acc[mi][ni][2] + b0, acc[mi][ni][3] + b1);
        }
    }
}

// ---------------------------------------------------------------------------
// LIF over t on fast proj; flag neurons with any |h - 1| < DELTA.
// ---------------------------------------------------------------------------
__global__ __launch_bounds__(256) void lif_flag_kernel()
{
    size_t i = (size_t)blockIdx.x * 256 + threadIdx.x;   // over LB*N3
    float v = 0.f;
    bool flag = false;
    #pragma unroll
    for (int t = 0; t < Tt; t++) {
        float x = g_proj[(size_t)t * LB * N3 + i];
        float h = v + (x - v) * 0.5f;
        flag |= fabsf(h - 1.0f) < DELTA;
        bool s = (h - 1.0f) >= 0.f;
        g_spk[(size_t)t * LB * N3 + i] = s ? 1 : 0;
        v = s ? 0.f : h;
    }
    if (flag) {
        unsigned int p = atomicAdd(&g_nflag, 1u);
        if (p < FIX_CAP) g_list[p] = (unsigned int)i;
    }
}

// ---------------------------------------------------------------------------
// Exact fixup: sequential-K fp32 FMA (bitwise-reference order).
// ---------------------------------------------------------------------------
__global__ __launch_bounds__(256) void fixup_kernel(
    const float* __restrict__ Q, const float* __restrict__ W,
    const float* __restrict__ bias)
{
    unsigned int tid = blockIdx.x * 256 + threadIdx.x;
    unsigned int n = g_nflag; if (n > FIX_CAP) n = FIX_CAP;
    if (tid >= n) return;
    unsigned int i = g_list[tid];
    int lb = i / N3;
    int f  = i - lb * N3;

    const float* wr = W + (size_t)f * Ee;
    float acc[4] = {0.f, 0.f, 0.f, 0.f};
    for (int k = 0; k < Ee; k += 4) {
        float4 wv = *(const float4*)(wr + k);
        #pragma unroll
        for (int t = 0; t < Tt; t++) {
            const float* qr = Q + ((size_t)t * LB + lb) * Ee + k;
            float4 qv = *(const float4*)qr;
            acc[t] = fmaf(qv.x, wv.x, acc[t]);
            acc[t] = fmaf(qv.y, wv.y, acc[t]);
            acc[t] = fmaf(qv.z, wv.z, acc[t]);
            acc[t] = fmaf(qv.w, wv.w, acc[t]);
        }
    }
    float b = bias[f];
    float v = 0.f;
    #pragma unroll
    for (int t = 0; t < Tt; t++) {
        float x = acc[t] + b;
        float h = v + (x - v) * 0.5f;
        bool s = (h - 1.0f) >= 0.f;
        g_spk[(size_t)t * LB * N3 + i] = s ? 1 : 0;
        v = s ? 0.f : h;
    }
}

// ---------------------------------------------------------------------------
// kv attention on tensor cores: attnT[t,n][e][d] = sum_l v[l,e] * k[l,d].
// (Validated R9: exact integer counts, no atomics.)
// ---------------------------------------------------------------------------
__global__ __launch_bounds__(256) void kv_attn_kernel()
{
    const int n = blockIdx.x, t = blockIdx.y;
    const int b = n >> 3, h = n & 7;
    __shared__ __half vT[64 * KVS];   // [e][l]
    __shared__ __half kT[64 * KVS];   // [d][l]

    const int tid  = threadIdx.x;
    const int wid  = tid >> 5;
    const int lane = tid & 31;
    const int e0 = (wid >> 1) * 16;
    const int d0 = (wid & 1) * 32;
    const int lr = lane >> 2;
    const int lc = (lane & 3) * 2;

    const int a_r = lane & 15, a_k = (lane >> 4) * 8;
    const int b_r = (lane & 7) + ((lane >> 4) << 3);
    const int b_k = ((lane >> 3) & 1) * 8;

    float acc[4][4];
    #pragma unroll
    for (int ni = 0; ni < 4; ni++)
        #pragma unroll
        for (int r = 0; r < 4; r++) acc[ni][r] = 0.f;

    for (int l0 = 0; l0 < Ll; l0 += 128) {
        __syncthreads();
        for (int i = tid; i < 2048; i += 256) {
            int ll = i >> 4, d4 = (i & 15) << 2;
            size_t base = ((size_t)t * LB + (size_t)(l0 + ll) * Bb + b) * N3
                          + h * 64 + d4;
            uchar4 kc = *(const uchar4*)(g_spk + base + 512);
            uchar4 vc = *(const uchar4*)(g_spk + base + 1024);
            kT[(d4+0)*KVS + ll] = __ushort_as_half(H1(kc.x));
            kT[(d4+1)*KVS + ll] = __ushort_as_half(H1(kc.y));
            kT[(d4+2)*KVS + ll] = __ushort_as_half(H1(kc.z));
            kT[(d4+3)*KVS + ll] = __ushort_as_half(H1(kc.w));
            vT[(d4+0)*KVS + ll] = __ushort_as_half(H1(vc.x));
            vT[(d4+1)*KVS + ll] = __ushort_as_half(H1(vc.y));
            vT[(d4+2)*KVS + ll] = __ushort_as_half(H1(vc.z));
            vT[(d4+3)*KVS + ll] = __ushort_as_half(H1(vc.w));
        }
        __syncthreads();

        #pragma unroll
        for (int kk = 0; kk < 128; kk += 16) {
            uint32_t a[4];
            ldsm_x4(a[0], a[1], a[2], a[3], &vT[(e0 + a_r)*KVS + kk + a_k]);
            uint32_t bt[4][2];
            #pragma unroll
            for (int nb = 0; nb < 2; nb++)
                ldsm_x4(bt[nb*2][0], bt[nb*2][1], bt[nb*2+1][0], bt[nb*2+1][1],
                        &kT[(d0 + nb*16 + b_r)*KVS + kk + b_k]);
            #pragma unroll
            for (int ni = 0; ni < 4; ni++)
                MMA_F16(acc[ni], a[0], a[1], a[2], a[3], bt[ni][0], bt[ni][1]);
        }
    }

    __half* ap = g_attn + (size_t)(t * 64 + n) * 4096;
    #pragma unroll
    for (int ni = 0; ni < 4; ni++) {
        int d = d0 + ni*8 + lc;
        *(__half2*)(ap + (e0 + lr) * 64 + d) =
            __floats2half2_rn(acc[ni][0], acc[ni][1]);
        *(__half2*)(ap + (e0 + lr + 8) * 64 + d) =
            __floats2half2_rn(acc[ni][2], acc[ni][3]);
    }
}

// ---------------------------------------------------------------------------
// q @ attn on tensor cores + fused LIF(0.5). (Validated R9: exact.)
// ---------------------------------------------------------------------------
__global__ __launch_bounds__(256) void qattn_lif_kernel()
{
    const int n = blockIdx.y, lt = blockIdx.x;
    const int b = n >> 3, h = n & 7;
    __shared__ __half qs[128][72];
    __shared__ __half at[64][72];

    const int tid  = threadIdx.x;
    const int wid  = tid >> 5;
    const int lane = tid & 31;
    const int wm = wid >> 1;
    const int wn = wid & 1;
    const int lr = lane >> 2;
    const int lc = (lane & 3) * 2;

    const int a_r = lane & 15, a_k = (lane >> 4) * 8;
    const int b_r = (lane & 7) + ((lane >> 4) << 3);
    const int b_k = ((lane >> 3) & 1) * 8;

    float vmem[2][4][4];
    #pragma unroll
    for (int mi = 0; mi < 2; mi++)
        #pragma unroll
        for (int ni = 0; ni < 4; ni++)
            #pragma unroll
            for (int r = 0; r < 4; r++) vmem[mi][ni][r] = 0.f;

    for (int t = 0; t < Tt; t++) {
        __syncthreads();
        for (int i = tid; i < 2048; i += 256) {
            int ll = i >> 4, d4 = (i & 15) << 2;
            size_t base = ((size_t)t * LB + (size_t)(lt*128 + ll) * Bb + b) * N3
                          + h * 64 + d4;
            uchar4 qc = *(const uchar4*)(g_spk + base);
            unsigned short hh[4] = {H1(qc.x), H1(qc.y), H1(qc.z), H1(qc.w)};
            *(uint2*)&qs[ll][d4] = *(uint2*)hh;
        }
        for (int i = tid; i < 512; i += 256) {
            int row = i >> 3, c8 = (i & 7) << 3;
            *(uint4*)&at[row][c8] =
                *(const uint4*)(g_attn + (size_t)(t*64 + n) * 4096 + row*64 + c8);
        }
        __syncthreads();

        float acc[2][4][4];
        #pragma unroll
        for (int mi = 0; mi < 2; mi++)
            #pragma unroll
            for (int ni = 0; ni < 4; ni++)
                #pragma unroll
                for (int r = 0; r < 4; r++) acc[mi][ni][r] = 0.f;

        #pragma unroll
        for (int kk = 0; kk < 64; kk += 16) {
            uint32_t a[2][4];
            #pragma unroll
            for (int mi = 0; mi < 2; mi++)
                ldsm_x4(a[mi][0], a[mi][1], a[mi][2], a[mi][3],
                        &qs[wm*32 + mi*16 + a_r][kk + a_k]);
            uint32_t bt[4][2];
            #pragma unroll
            for (int nb = 0; nb < 2; nb++)
                ldsm_x4(bt[nb*2][0], bt[nb*2][1], bt[nb*2+1][0], bt[nb*2+1][1],
                        &at[wn*32 + nb*16 + b_r][kk + b_k]);
            #pragma unroll
            for (int ni = 0; ni < 4; ni++)
                #pragma unroll
                for (int mi = 0; mi < 2; mi++)
                    MMA_F16(acc[mi][ni], a[mi][0], a[mi][1], a[mi][2], a[mi][3],
                            bt[ni][0], bt[ni][1]);
        }

        #pragma unroll
        for (int mi = 0; mi < 2; mi++) {
            #pragma unroll
            for (int ni = 0; ni < 4; ni++) {
                int e = wn*32 + ni*8 + lc;
                #pragma unroll
                for (int rp = 0; rp < 2; rp++) {
                    int l = lt*128 + wm*32 + mi*16 + lr + rp*8;
                    unsigned short sp[2];
                    #pragma unroll
                    for (int c = 0; c < 2; c++) {
                        int r = rp*2 + c;
                        float x = acc[mi][ni][r] * 0.125f;
                        float v = vmem[mi][ni][r];
                        float hh = v + (x - v) * 0.5f;
                        bool s = (hh - 0.5f) >= 0.f;
                        sp[c] = s ? 0x3C00 : 0;
                        vmem[mi][ni][r] = s ? 0.f : hh;
                    }
                    *(uint32_t*)(g_s2 + (((size_t)t * Ll + l) * Bb + b) * Ee
                                 + h * 64 + e) = *(uint32_t*)sp;
                }
            }
        }
    }
}

// ---------------------------------------------------------------------------
// Split W_out into fp16 hi + lo
// ---------------------------------------------------------------------------
__global__ __launch_bounds__(256) void wsplit_kernel(const float* __restrict__ W)
{
    int i = blockIdx.x * 256 + threadIdx.x;
    float w = W[i];
    __half hi = __float2half_rn(w);
    g_whi[i] = hi;
    g_wlo[i] = __float2half_rn(w - __half2float(hi));
}

// ---------------------------------------------------------------------------
// GEMM5: out = s2 @ (Whi + Wlo)^T + bias, fp16 split, ldmatrix + cp.async.
// ---------------------------------------------------------------------------
__global__ __launch_bounds__(256) void gemm5_mma_kernel(
    const float* __restrict__ bias, float* __restrict__ C)
{
    extern __shared__ __half dsm[];
    __half* As  = dsm;              // [2][128][40]
    __half* Bhi = dsm + 2*STG;
    __half* Blo = dsm + 4*STG;

    const int bm = blockIdx.y * 128;
    const int bn = blockIdx.x * 128;
    const int tid  = threadIdx.x;
    const int wid  = tid >> 5;
    const int lane = tid & 31;
    const int wm = wid >> 1;
    const int wn = wid & 1;
    const int lr = lane >> 2;
    const int lc = (lane & 3) * 2;

    const int a_r = lane & 15, a_k = (lane >> 4) * 8;
    const int b_r = (lane & 7) + ((lane >> 4) << 3);
    const int b_k = ((lane >> 3) & 1) * 8;

    float acc[2][8][4];
    #pragma unroll
    for (int mi = 0; mi < 2; mi++)
        #pragma unroll
        for (int ni = 0; ni < 8; ni++)
            #pragma unroll
            for (int r = 0; r < 4; r++) acc[mi][ni][r] = 0.f;

    auto load_stage = [&](int s, int k0) {
        #pragma unroll
        for (int i = tid; i < 512; i += 256) {
            int row = i >> 2, c8 = (i & 3) << 3;
            int so = s*STG + row*40 + c8;
            cp16(As + so, g_s2 + (size_t)(bm + row) * Ee + k0 + c8);
            size_t off = (size_t)(bn + row) * Ee + k0 + c8;
            cp16(Bhi + so, g_whi + off);
            cp16(Blo + so, g_wlo + off);
        }
    };

    load_stage(0, 0);
    CP_COMMIT();

    const int NT = Ee / 32;
    for (int it = 0; it < NT; it++) {
        if (it + 1 < NT) {
            load_stage((it + 1) & 1, (it + 1) * 32);
            CP_COMMIT();
            CP_WAIT1();
        } else {
            CP_WAIT0();
        }
        __syncthreads();

        const int sb = (it & 1) * STG;
        #pragma unroll
        for (int kk = 0; kk < 32; kk += 16) {
            uint32_t a[2][4];
            #pragma unroll
            for (int mi = 0; mi < 2; mi++) {
                int rb = wm*32 + mi*16;
                ldsm_x4(a[mi][0], a[mi][1], a[mi][2], a[mi][3],
                        As + sb + (rb + a_r)*40 + kk + a_k);
            }
            uint32_t bh[8][2], bl[8][2];
            #pragma unroll
            for (int nb = 0; nb < 4; nb++) {
                int n0 = wn*64 + nb*16;
                ldsm_x4(bh[nb*2][0], bh[nb*2][1], bh[nb*2+1][0], bh[nb*2+1][1],
                        Bhi + sb + (n0 + b_r)*40 + kk + b_k);
                ldsm_x4(bl[nb*2][0], bl[nb*2][1], bl[nb*2+1][0], bl[nb*2+1][1],
                        Blo + sb + (n0 + b_r)*40 + kk + b_k);
            }
            #pragma unroll
            for (int ni = 0; ni < 8; ni++) {
                #pragma unroll
                for (int mi = 0; mi < 2; mi++) {
                    MMA_F16(acc[mi][ni], a[mi][0], a[mi][1], a[mi][2], a[mi][3],
                            bh[ni][0], bh[ni][1]);
                    MMA_F16(acc[mi][ni], a[mi][0], a[mi][1], a[mi][2], a[mi][3],
                            bl[ni][0], bl[ni][1]);
                }
            }
        }
        __syncthreads();
    }

    #pragma unroll
    for (int mi = 0; mi < 2; mi++) {
        #pragma unroll
        for (int ni = 0; ni < 8; ni++) {
            int col = bn + wn*64 + ni*8 + lc;
            float b0 = bias[col], b1 = bias[col + 1];
            int row0 = bm + wm*32 + mi*16 + lr;
            *(float2*)(C + (size_t)row0 * Ee + col) =
                make_float2(acc[mi][ni][0] + b0, acc[mi][ni][1] + b1);
            *(float2*)(C + (size_t)(row0 + 8) * Ee + col) =
                make_float2(acc[mi][ni][2] + b0, acc[mi][ni][3] + b1);
        }
    }
}

// ---------------------------------------------------------------------------
extern "C" void kernel_launch(void* const* d_in, const int* in_sizes, int n_in,
                              void* d_out, int out_size)
{
    const float* query = (const float*)d_in[0];   // (T,L,B,E)
    const float* w_in  = (const float*)d_in[1];   // (3E, E)
    const float* b_in  = (const float*)d_in[2];   // (3E)
    const float* w_out = (const float*)d_in[3];   // (E, E)
    const float* b_out = (const float*)d_in[4];   // (E)
    float* out = (float*)d_out;                   // (T,L,B,E)

    void *p_a0, *p_a1, *p_w0;
    cudaGetSymbolAddress(&p_a0, g_a0);
    cudaGetSymbolAddress(&p_a1, g_a1);
    cudaGetSymbolAddress(&p_w0, g_w0);

    // 0) zero flag counter + fp16 splits/converts
    zero_flag_kernel<<<1, 1>>>();
    split_kernel<<<((size_t)Mm * Ee / 4) / 256, 256>>>(
        query, (__half*)p_a0, (__half*)p_a1);
    conv_kernel<<<((size_t)N3 * Ee / 4) / 256, 256>>>(w_in, (__half*)p_w0);
    wsplit_kernel<<<(Ee * Ee) / 256, 256>>>(w_out);

    // 1) fast proj on tensor cores (2-pass fp16 split)
    const int SM1 = 6 * STG * (int)sizeof(__half);   // 60 KB
    cudaFuncSetAttribute(gemm1_fast_kernel,
                         cudaFuncAttributeMaxDynamicSharedMemorySize, SM1);
    gemm1_fast_kernel<<<dim3(N3 / 128, Mm / 128), 256, SM1>>>(b_in);

    // 2) LIF + flag marginal neurons (DELTA=2.5e-3), then exact fixup
    lif_flag_kernel<<<((size_t)LB * N3) / 256, 256>>>();
    fixup_kernel<<<FIX_CAP / 256, 256>>>(query, w_in, b_in);

    // 3) attnT = v^T k per (t, head) on tensor cores
    kv_attn_kernel<<<dim3(64, Tt), 256>>>();

    // 4) out = q @ attn * 0.125 -> LIF(0.5) -> s2 spikes, tensor cores
    qattn_lif_kernel<<<dim3(Ll / 128, 64), 256>>>();

    // 5) final = s2 @ W_out^T + b_out on tensor cores
    const int SM5 = 6 * STG * (int)sizeof(__half);   // 60 KB
    cudaFuncSetAttribute(gemm5_mma_kernel,
                         cudaFuncAttributeMaxDynamicSharedMemorySize, SM5);
    gemm5_mma_kernel<<<dim3(Ee / 128, Mm / 128), 256, SM5>>>(b_out, out);
}

// round 12
// speedup vs baseline: 1.3246x; 1.1237x over previous
#include <cuda_runtime.h>
#include <cuda_fp16.h>
#include <cstdint>

// Problem dims (fixed)
#define Tt 4
#define Ll 2048
#define Bb 8
#define Ee 512
#define LB (Ll*Bb)        // 16384
#define Mm (Tt*LB)        // 65536
#define N3 (3*Ee)         // 1536
#define FIX_CAP (1u<<20)
#define DELTA 4e-3f

// Scratch (device globals, allocation-free rule)
static __device__ float    g_proj[(size_t)Mm * N3];   // fast proj
static __device__ __half   g_a0  [(size_t)Mm * Ee];   // query (fp16)
static __device__ __half   g_w0  [N3 * Ee];           // W_in (fp16)
static __device__ uint8_t  g_spk [(size_t)Mm * N3];   // qkv spikes
static __device__ __half   g_attn[Tt * 64 * 64 * 64]; // attn^T counts (exact fp16)
static __device__ __half   g_s2  [(size_t)Mm * Ee];   // s2 spikes (fp16 0/1)
static __device__ __half   g_whi [Ee * Ee];           // W_out hi
static __device__ __half   g_wlo [Ee * Ee];           // W_out lo
static __device__ unsigned int g_nflag;
static __device__ unsigned int g_list[FIX_CAP];

__device__ __forceinline__ void ldsm_x4(uint32_t& r0, uint32_t& r1,
                                        uint32_t& r2, uint32_t& r3,
                                        const void* p)
{
    uint32_t a = (uint32_t)__cvta_generic_to_shared(p);
    asm volatile("ldmatrix.sync.aligned.m8n8.x4.shared.b16 {%0,%1,%2,%3}, [%4];"
                 : "=r"(r0), "=r"(r1), "=r"(r2), "=r"(r3) : "r"(a));
}

__device__ __forceinline__ void cp16(void* dst, const void* src)
{
    uint32_t d = (uint32_t)__cvta_generic_to_shared(dst);
    asm volatile("cp.async.cg.shared.global [%0], [%1], 16;" :: "r"(d), "l"(src));
}
#define CP_COMMIT() asm volatile("cp.async.commit_group;")
#define CP_WAIT1()  asm volatile("cp.async.wait_group 1;")
#define CP_WAIT0()  asm volatile("cp.async.wait_group 0;")

#define MMA_F16(acc, a0, a1, a2, a3, b0, b1)                                \
    asm volatile(                                                           \
        "mma.sync.aligned.m16n8k16.row.col.f32.f16.f16.f32 "                \
        "{%0,%1,%2,%3}, {%4,%5,%6,%7}, {%8,%9}, {%0,%1,%2,%3};"             \
        : "+f"(acc[0]), "+f"(acc[1]), "+f"(acc[2]), "+f"(acc[3])            \
        : "r"(a0), "r"(a1), "r"(a2), "r"(a3), "r"(b0), "r"(b1))

// gemm stage stride: 128 rows x 40 halves
#define STG 5120
// kv transpose tile stride (halves): 272 bytes, 16B-aligned rows for ldmatrix
#define KVS 136
// spike (0/1) -> fp16 bit pattern
#define H1(u) ((unsigned short)((u) * 0x3C00u))

// ---------------------------------------------------------------------------
// fp32 -> fp16 convert (query, W_in) and hi/lo split (W_out)
// ---------------------------------------------------------------------------
__global__ __launch_bounds__(256) void conv_kernel(
    const float* __restrict__ src, __half* __restrict__ d0)
{
    size_t i4 = ((size_t)blockIdx.x * 256 + threadIdx.x) * 4;
    float4 v = *(const float4*)(src + i4);
    __half h[4] = {__float2half_rn(v.x), __float2half_rn(v.y),
                   __float2half_rn(v.z), __float2half_rn(v.w)};
    *(uint2*)(d0 + i4) = *(uint2*)h;
}

__global__ void zero_flag_kernel() { g_nflag = 0u; }

// ---------------------------------------------------------------------------
// GEMM1 fast path: proj = q @ W_in^T + bias, single pure-fp16 mma pass.
// Dropped a1*w + a*w1 terms (sigma ~2.1e-4) are repaired by the exact fixup
// (DELTA = 4e-3 ~ 19 sigma). ldmatrix + cp.async 2-stage pipeline.
// Block 128x128, 8 warps (4m x 2n). smem 40 KB.
// ---------------------------------------------------------------------------
__global__ __launch_bounds__(256) void gemm1_fast_kernel(
    const float* __restrict__ bias)
{
    extern __shared__ __half dsm[];
    __half* A0s = dsm;              // [2][128][40]
    __half* B0s = dsm + 2*STG;

    const int bm = blockIdx.y * 128;
    const int bn = blockIdx.x * 128;
    const int tid  = threadIdx.x;
    const int wid  = tid >> 5;
    const int lane = tid & 31;
    const int wm = wid >> 1;
    const int wn = wid & 1;
    const int lr = lane >> 2;
    const int lc = (lane & 3) * 2;

    const int a_r = lane & 15, a_k = (lane >> 4) * 8;
    const int b_r = (lane & 7) + ((lane >> 4) << 3);
    const int b_k = ((lane >> 3) & 1) * 8;

    float acc[2][8][4];
    #pragma unroll
    for (int mi = 0; mi < 2; mi++)
        #pragma unroll
        for (int ni = 0; ni < 8; ni++)
            #pragma unroll
            for (int r = 0; r < 4; r++) acc[mi][ni][r] = 0.f;

    auto load_stage = [&](int s, int k0) {
        #pragma unroll
        for (int i = tid; i < 512; i += 256) {
            int row = i >> 2, c8 = (i & 3) << 3;
            int so = s*STG + row*40 + c8;
            cp16(A0s + so, g_a0 + (size_t)(bm + row) * Ee + k0 + c8);
            cp16(B0s + so, g_w0 + (size_t)(bn + row) * Ee + k0 + c8);
        }
    };

    load_stage(0, 0);
    CP_COMMIT();

    const int NT = Ee / 32;   // 16
    for (int it = 0; it < NT; it++) {
        if (it + 1 < NT) {
            load_stage((it + 1) & 1, (it + 1) * 32);
            CP_COMMIT();
            CP_WAIT1();
        } else {
            CP_WAIT0();
        }
        __syncthreads();

        const int sb = (it & 1) * STG;
        #pragma unroll
        for (int kk = 0; kk < 32; kk += 16) {
            uint32_t a0[2][4];
            #pragma unroll
            for (int mi = 0; mi < 2; mi++) {
                int rb = wm*32 + mi*16;
                ldsm_x4(a0[mi][0], a0[mi][1], a0[mi][2], a0[mi][3],
                        A0s + sb + (rb + a_r)*40 + kk + a_k);
            }
            uint32_t bh[8][2];
            #pragma unroll
            for (int nb = 0; nb < 4; nb++) {
                int n0 = wn*64 + nb*16;
                ldsm_x4(bh[nb*2][0], bh[nb*2][1], bh[nb*2+1][0], bh[nb*2+1][1],
                        B0s + sb + (n0 + b_r)*40 + kk + b_k);
            }
            #pragma unroll
            for (int ni = 0; ni < 8; ni++) {
                #pragma unroll
                for (int mi = 0; mi < 2; mi++) {
                    MMA_F16(acc[mi][ni], a0[mi][0], a0[mi][1], a0[mi][2],
                            a0[mi][3], bh[ni][0], bh[ni][1]);
                }
            }
        }
        __syncthreads();
    }

    #pragma unroll
    for (int mi = 0; mi < 2; mi++) {
        #pragma unroll
        for (int ni = 0; ni < 8; ni++) {
            int col = bn + wn*64 + ni*8 + lc;
            float b0 = bias[col], b1 = bias[col + 1];
            int row0 = bm + wm*32 + mi*16 + lr;
            *(float2*)(g_proj + (size_t)row0 * N3 + col) =
                make_float2(acc[mi][ni][0] + b0, acc[mi][ni][1] + b1);
            *(float2*)(g_proj + (size_t)(row0 + 8) * N3 + col) =
                make_float2(acc[mi][ni][2] + b0, acc[mi][ni][3] + b1);
        }
    }
}

// ---------------------------------------------------------------------------
// LIF over t on fast proj; flag neurons with any |h - 1| < DELTA.
// ---------------------------------------------------------------------------
__global__ __launch_bounds__(256) void lif_flag_kernel()
{
    size_t i = (size_t)blockIdx.x * 256 + threadIdx.x;   // over LB*N3
    float v = 0.f;
    bool flag = false;
    #pragma unroll
    for (int t = 0; t < Tt; t++) {
        float x = g_proj[(size_t)t * LB * N3 + i];
        float h = v + (x - v) * 0.5f;
        flag |= fabsf(h - 1.0f) < DELTA;
        bool s = (h - 1.0f) >= 0.f;
        g_spk[(size_t)t * LB * N3 + i] = s ? 1 : 0;
        v = s ? 0.f : h;
    }
    if (flag) {
        unsigned int p = atomicAdd(&g_nflag, 1u);
        if (p < FIX_CAP) g_list[p] = (unsigned int)i;
    }
}

// ---------------------------------------------------------------------------
// Exact fixup: sequential-K fp32 FMA (bitwise-reference order).
// ---------------------------------------------------------------------------
__global__ __launch_bounds__(256) void fixup_kernel(
    const float* __restrict__ Q, const float* __restrict__ W,
    const float* __restrict__ bias)
{
    unsigned int tid = blockIdx.x * 256 + threadIdx.x;
    unsigned int n = g_nflag; if (n > FIX_CAP) n = FIX_CAP;
    if (tid >= n) return;
    unsigned int i = g_list[tid];
    int lb = i / N3;
    int f  = i - lb * N3;

    const float* wr = W + (size_t)f * Ee;
    float acc[4] = {0.f, 0.f, 0.f, 0.f};
    for (int k = 0; k < Ee; k += 4) {
        float4 wv = *(const float4*)(wr + k);
        #pragma unroll
        for (int t = 0; t < Tt; t++) {
            const float* qr = Q + ((size_t)t * LB + lb) * Ee + k;
            float4 qv = *(const float4*)qr;
            acc[t] = fmaf(qv.x, wv.x, acc[t]);
            acc[t] = fmaf(qv.y, wv.y, acc[t]);
            acc[t] = fmaf(qv.z, wv.z, acc[t]);
            acc[t] = fmaf(qv.w, wv.w, acc[t]);
        }
    }
    float b = bias[f];
    float v = 0.f;
    #pragma unroll
    for (int t = 0; t < Tt; t++) {
        float x = acc[t] + b;
        float h = v + (x - v) * 0.5f;
        bool s = (h - 1.0f) >= 0.f;
        g_spk[(size_t)t * LB * N3 + i] = s ? 1 : 0;
        v = s ? 0.f : h;
    }
}

// ---------------------------------------------------------------------------
// kv attention on tensor cores: attnT[t,n][e][d] = sum_l v[l,e] * k[l,d].
// (Validated R9: exact integer counts, no atomics.)
// ---------------------------------------------------------------------------
__global__ __launch_bounds__(256) void kv_attn_kernel()
{
    const int n = blockIdx.x, t = blockIdx.y;
    const int b = n >> 3, h = n & 7;
    __shared__ __half vT[64 * KVS];   // [e][l]
    __shared__ __half kT[64 * KVS];   // [d][l]

    const int tid  = threadIdx.x;
    const int wid  = tid >> 5;
    const int lane = tid & 31;
    const int e0 = (wid >> 1) * 16;
    const int d0 = (wid & 1) * 32;
    const int lr = lane >> 2;
    const int lc = (lane & 3) * 2;

    const int a_r = lane & 15, a_k = (lane >> 4) * 8;
    const int b_r = (lane & 7) + ((lane >> 4) << 3);
    const int b_k = ((lane >> 3) & 1) * 8;

    float acc[4][4];
    #pragma unroll
    for (int ni = 0; ni < 4; ni++)
        #pragma unroll
        for (int r = 0; r < 4; r++) acc[ni][r] = 0.f;

    for (int l0 = 0; l0 < Ll; l0 += 128) {
        __syncthreads();
        for (int i = tid; i < 2048; i += 256) {
            int ll = i >> 4, d4 = (i & 15) << 2;
            size_t base = ((size_t)t * LB + (size_t)(l0 + ll) * Bb + b) * N3
                          + h * 64 + d4;
            uchar4 kc = *(const uchar4*)(g_spk + base + 512);
            uchar4 vc = *(const uchar4*)(g_spk + base + 1024);
            kT[(d4+0)*KVS + ll] = __ushort_as_half(H1(kc.x));
            kT[(d4+1)*KVS + ll] = __ushort_as_half(H1(kc.y));
            kT[(d4+2)*KVS + ll] = __ushort_as_half(H1(kc.z));
            kT[(d4+3)*KVS + ll] = __ushort_as_half(H1(kc.w));
            vT[(d4+0)*KVS + ll] = __ushort_as_half(H1(vc.x));
            vT[(d4+1)*KVS + ll] = __ushort_as_half(H1(vc.y));
            vT[(d4+2)*KVS + ll] = __ushort_as_half(H1(vc.z));
            vT[(d4+3)*KVS + ll] = __ushort_as_half(H1(vc.w));
        }
        __syncthreads();

        #pragma unroll
        for (int kk = 0; kk < 128; kk += 16) {
            uint32_t a[4];
            ldsm_x4(a[0], a[1], a[2], a[3], &vT[(e0 + a_r)*KVS + kk + a_k]);
            uint32_t bt[4][2];
            #pragma unroll
            for (int nb = 0; nb < 2; nb++)
                ldsm_x4(bt[nb*2][0], bt[nb*2][1], bt[nb*2+1][0], bt[nb*2+1][1],
                        &kT[(d0 + nb*16 + b_r)*KVS + kk + b_k]);
            #pragma unroll
            for (int ni = 0; ni < 4; ni++)
                MMA_F16(acc[ni], a[0], a[1], a[2], a[3], bt[ni][0], bt[ni][1]);
        }
    }

    __half* ap = g_attn + (size_t)(t * 64 + n) * 4096;
    #pragma unroll
    for (int ni = 0; ni < 4; ni++) {
        int d = d0 + ni*8 + lc;
        *(__half2*)(ap + (e0 + lr) * 64 + d) =
            __floats2half2_rn(acc[ni][0], acc[ni][1]);
        *(__half2*)(ap + (e0 + lr + 8) * 64 + d) =
            __floats2half2_rn(acc[ni][2], acc[ni][3]);
    }
}

// ---------------------------------------------------------------------------
// q @ attn on tensor cores + fused LIF(0.5). (Validated R9: exact.)
// ---------------------------------------------------------------------------
__global__ __launch_bounds__(256) void qattn_lif_kernel()
{
    const int n = blockIdx.y, lt = blockIdx.x;
    const int b = n >> 3, h = n & 7;
    __shared__ __half qs[128][72];
    __shared__ __half at[64][72];

    const int tid  = threadIdx.x;
    const int wid  = tid >> 5;
    const int lane = tid & 31;
    const int wm = wid >> 1;
    const int wn = wid & 1;
    const int lr = lane >> 2;
    const int lc = (lane & 3) * 2;

    const int a_r = lane & 15, a_k = (lane >> 4) * 8;
    const int b_r = (lane & 7) + ((lane >> 4) << 3);
    const int b_k = ((lane >> 3) & 1) * 8;

    float vmem[2][4][4];
    #pragma unroll
    for (int mi = 0; mi < 2; mi++)
        #pragma unroll
        for (int ni = 0; ni < 4; ni++)
            #pragma unroll
            for (int r = 0; r < 4; r++) vmem[mi][ni][r] = 0.f;

    for (int t = 0; t < Tt; t++) {
        __syncthreads();
        for (int i = tid; i < 2048; i += 256) {
            int ll = i >> 4, d4 = (i & 15) << 2;
            size_t base = ((size_t)t * LB + (size_t)(lt*128 + ll) * Bb + b) * N3
                          + h * 64 + d4;
            uchar4 qc = *(const uchar4*)(g_spk + base);
            unsigned short hh[4] = {H1(qc.x), H1(qc.y), H1(qc.z), H1(qc.w)};
            *(uint2*)&qs[ll][d4] = *(uint2*)hh;
        }
        for (int i = tid; i < 512; i += 256) {
            int row = i >> 3, c8 = (i & 7) << 3;
            *(uint4*)&at[row][c8] =
                *(const uint4*)(g_attn + (size_t)(t*64 + n) * 4096 + row*64 + c8);
        }
        __syncthreads();

        float acc[2][4][4];
        #pragma unroll
        for (int mi = 0; mi < 2; mi++)
            #pragma unroll
            for (int ni = 0; ni < 4; ni++)
                #pragma unroll
                for (int r = 0; r < 4; r++) acc[mi][ni][r] = 0.f;

        #pragma unroll
        for (int kk = 0; kk < 64; kk += 16) {
            uint32_t a[2][4];
            #pragma unroll
            for (int mi = 0; mi < 2; mi++)
                ldsm_x4(a[mi][0], a[mi][1], a[mi][2], a[mi][3],
                        &qs[wm*32 + mi*16 + a_r][kk + a_k]);
            uint32_t bt[4][2];
            #pragma unroll
            for (int nb = 0; nb < 2; nb++)
                ldsm_x4(bt[nb*2][0], bt[nb*2][1], bt[nb*2+1][0], bt[nb*2+1][1],
                        &at[wn*32 + nb*16 + b_r][kk + b_k]);
            #pragma unroll
            for (int ni = 0; ni < 4; ni++)
                #pragma unroll
                for (int mi = 0; mi < 2; mi++)
                    MMA_F16(acc[mi][ni], a[mi][0], a[mi][1], a[mi][2], a[mi][3],
                            bt[ni][0], bt[ni][1]);
        }

        #pragma unroll
        for (int mi = 0; mi < 2; mi++) {
            #pragma unroll
            for (int ni = 0; ni < 4; ni++) {
                int e = wn*32 + ni*8 + lc;
                #pragma unroll
                for (int rp = 0; rp < 2; rp++) {
                    int l = lt*128 + wm*32 + mi*16 + lr + rp*8;
                    unsigned short sp[2];
                    #pragma unroll
                    for (int c = 0; c < 2; c++) {
                        int r = rp*2 + c;
                        float x = acc[mi][ni][r] * 0.125f;
                        float v = vmem[mi][ni][r];
                        float hh = v + (x - v) * 0.5f;
                        bool s = (hh - 0.5f) >= 0.f;
                        sp[c] = s ? 0x3C00 : 0;
                        vmem[mi][ni][r] = s ? 0.f : hh;
                    }
                    *(uint32_t*)(g_s2 + (((size_t)t * Ll + l) * Bb + b) * Ee
                                 + h * 64 + e) = *(uint32_t*)sp;
                }
            }
        }
    }
}

// ---------------------------------------------------------------------------
// Split W_out into fp16 hi + lo
// ---------------------------------------------------------------------------
__global__ __launch_bounds__(256) void wsplit_kernel(const float* __restrict__ W)
{
    int i = blockIdx.x * 256 + threadIdx.x;
    float w = W[i];
    __half hi = __float2half_rn(w);
    g_whi[i] = hi;
    g_wlo[i] = __float2half_rn(w - __half2float(hi));
}

// ---------------------------------------------------------------------------
// GEMM5: out = s2 @ (Whi + Wlo)^T + bias, fp16 split, ldmatrix + cp.async.
// (2 passes kept: GEMM5 error hits rel_err directly, no fixup possible.)
// ---------------------------------------------------------------------------
__global__ __launch_bounds__(256) void gemm5_mma_kernel(
    const float* __restrict__ bias, float* __restrict__ C)
{
    extern __shared__ __half dsm[];
    __half* As  = dsm;              // [2][128][40]
    __half* Bhi = dsm + 2*STG;
    __half* Blo = dsm + 4*STG;

    const int bm = blockIdx.y * 128;
    const int bn = blockIdx.x * 128;
    const int tid  = threadIdx.x;
    const int wid  = tid >> 5;
    const int lane = tid & 31;
    const int wm = wid >> 1;
    const int wn = wid & 1;
    const int lr = lane >> 2;
    const int lc = (lane & 3) * 2;

    const int a_r = lane & 15, a_k = (lane >> 4) * 8;
    const int b_r = (lane & 7) + ((lane >> 4) << 3);
    const int b_k = ((lane >> 3) & 1) * 8;

    float acc[2][8][4];
    #pragma unroll
    for (int mi = 0; mi < 2; mi++)
        #pragma unroll
        for (int ni = 0; ni < 8; ni++)
            #pragma unroll
            for (int r = 0; r < 4; r++) acc[mi][ni][r] = 0.f;

    auto load_stage = [&](int s, int k0) {
        #pragma unroll
        for (int i = tid; i < 512; i += 256) {
            int row = i >> 2, c8 = (i & 3) << 3;
            int so = s*STG + row*40 + c8;
            cp16(As + so, g_s2 + (size_t)(bm + row) * Ee + k0 + c8);
            size_t off = (size_t)(bn + row) * Ee + k0 + c8;
            cp16(Bhi + so, g_whi + off);
            cp16(Blo + so, g_wlo + off);
        }
    };

    load_stage(0, 0);
    CP_COMMIT();

    const int NT = Ee / 32;
    for (int it = 0; it < NT; it++) {
        if (it + 1 < NT) {
            load_stage((it + 1) & 1, (it + 1) * 32);
            CP_COMMIT();
            CP_WAIT1();
        } else {
            CP_WAIT0();
        }
        __syncthreads();

        const int sb = (it & 1) * STG;
        #pragma unroll
        for (int kk = 0; kk < 32; kk += 16) {
            uint32_t a[2][4];
            #pragma unroll
            for (int mi = 0; mi < 2; mi++) {
                int rb = wm*32 + mi*16;
                ldsm_x4(a[mi][0], a[mi][1], a[mi][2], a[mi][3],
                        As + sb + (rb + a_r)*40 + kk + a_k);
            }
            uint32_t bh[8][2], bl[8][2];
            #pragma unroll
            for (int nb = 0; nb < 4; nb++) {
                int n0 = wn*64 + nb*16;
                ldsm_x4(bh[nb*2][0], bh[nb*2][1], bh[nb*2+1][0], bh[nb*2+1][1],
                        Bhi + sb + (n0 + b_r)*40 + kk + b_k);
                ldsm_x4(bl[nb*2][0], bl[nb*2][1], bl[nb*2+1][0], bl[nb*2+1][1],
                        Blo + sb + (n0 + b_r)*40 + kk + b_k);
            }
            #pragma unroll
            for (int ni = 0; ni < 8; ni++) {
                #pragma unroll
                for (int mi = 0; mi < 2; mi++) {
                    MMA_F16(acc[mi][ni], a[mi][0], a[mi][1], a[mi][2], a[mi][3],
                            bh[ni][0], bh[ni][1]);
                    MMA_F16(acc[mi][ni], a[mi][0], a[mi][1], a[mi][2], a[mi][3],
                            bl[ni][0], bl[ni][1]);
                }
            }
        }
        __syncthreads();
    }

    #pragma unroll
    for (int mi = 0; mi < 2; mi++) {
        #pragma unroll
        for (int ni = 0; ni < 8; ni++) {
            int col = bn + wn*64 + ni*8 + lc;
            float b0 = bias[col], b1 = bias[col + 1];
            int row0 = bm + wm*32 + mi*16 + lr;
            *(float2*)(C + (size_t)row0 * Ee + col) =
                make_float2(acc[mi][ni][0] + b0, acc[mi][ni][1] + b1);
            *(float2*)(C + (size_t)(row0 + 8) * Ee + col) =
                make_float2(acc[mi][ni][2] + b0, acc[mi][ni][3] + b1);
        }
    }
}

// ---------------------------------------------------------------------------
extern "C" void kernel_launch(void* const* d_in, const int* in_sizes, int n_in,
                              void* d_out, int out_size)
{
    const float* query = (const float*)d_in[0];   // (T,L,B,E)
    const float* w_in  = (const float*)d_in[1];   // (3E, E)
    const float* b_in  = (const float*)d_in[2];   // (3E)
    const float* w_out = (const float*)d_in[3];   // (E, E)
    const float* b_out = (const float*)d_in[4];   // (E)
    float* out = (float*)d_out;                   // (T,L,B,E)

    void *p_a0, *p_w0;
    cudaGetSymbolAddress(&p_a0, g_a0);
    cudaGetSymbolAddress(&p_w0, g_w0);

    // 0) zero flag counter + fp16 converts / W_out split
    zero_flag_kernel<<<1, 1>>>();
    conv_kernel<<<((size_t)Mm * Ee / 4) / 256, 256>>>(query, (__half*)p_a0);
    conv_kernel<<<((size_t)N3 * Ee / 4) / 256, 256>>>(w_in, (__half*)p_w0);
    wsplit_kernel<<<(Ee * Ee) / 256, 256>>>(w_out);

    // 1) fast proj on tensor cores (single pure-fp16 pass)
    const int SM1 = 4 * STG * (int)sizeof(__half);   // 40 KB
    cudaFuncSetAttribute(gemm1_fast_kernel,
                         cudaFuncAttributeMaxDynamicSharedMemorySize, SM1);
    gemm1_fast_kernel<<<dim3(N3 / 128, Mm / 128), 256, SM1>>>(b_in);

    // 2) LIF + flag marginal neurons (DELTA=4e-3), then exact fixup
    lif_flag_kernel<<<((size_t)LB * N3) / 256, 256>>>();
    fixup_kernel<<<FIX_CAP / 256, 256>>>(query, w_in, b_in);

    // 3) attnT = v^T k per (t, head) on tensor cores
    kv_attn_kernel<<<dim3(64, Tt), 256>>>();

    // 4) out = q @ attn * 0.125 -> LIF(0.5) -> s2 spikes, tensor cores
    qattn_lif_kernel<<<dim3(Ll / 128, 64), 256>>>();

    // 5) final = s2 @ W_out^T + b_out on tensor cores
    const int SM5 = 6 * STG * (int)sizeof(__half);   // 60 KB
    cudaFuncSetAttribute(gemm5_mma_kernel,
                         cudaFuncAttributeMaxDynamicSharedMemorySize, SM5);
    gemm5_mma_kernel<<<dim3(Ee / 128, Mm / 128), 256, SM5>>>(b_out, out);
}

// round 13
// speedup vs baseline: 1.4822x; 1.1190x over previous
#include <cuda_runtime.h>
#include <cuda_fp16.h>
#include <cstdint>

// Problem dims (fixed)
#define Tt 4
#define Ll 2048
#define Bb 8
#define Ee 512
#define LB (Ll*Bb)        // 16384
#define Mm (Tt*LB)        // 65536
#define N3 (3*Ee)         // 1536
#define FIX_CAP (1u<<20)
#define DELTA 2.5e-3f

// Scratch (device globals, allocation-free rule)
static __device__ float    g_proj[(size_t)Mm * N3];   // fast proj
static __device__ __half   g_a0  [(size_t)Mm * Ee];   // query (fp16)
static __device__ __half   g_w0  [N3 * Ee];           // W_in (fp16)
static __device__ uint8_t  g_spk [(size_t)Mm * N3];   // qkv spikes
static __device__ __half   g_attn[Tt * 64 * 64 * 64]; // attn^T counts (exact fp16)
static __device__ __half   g_s2  [(size_t)Mm * Ee];   // s2 spikes (fp16 0/1)
static __device__ __half   g_whi [Ee * Ee];           // W_out (fp16)
static __device__ unsigned int g_nflag;
static __device__ unsigned int g_list[FIX_CAP];

__device__ __forceinline__ void ldsm_x4(uint32_t& r0, uint32_t& r1,
                                        uint32_t& r2, uint32_t& r3,
                                        const void* p)
{
    uint32_t a = (uint32_t)__cvta_generic_to_shared(p);
    asm volatile("ldmatrix.sync.aligned.m8n8.x4.shared.b16 {%0,%1,%2,%3}, [%4];"
                 : "=r"(r0), "=r"(r1), "=r"(r2), "=r"(r3) : "r"(a));
}

__device__ __forceinline__ void cp16(void* dst, const void* src)
{
    uint32_t d = (uint32_t)__cvta_generic_to_shared(dst);
    asm volatile("cp.async.cg.shared.global [%0], [%1], 16;" :: "r"(d), "l"(src));
}
#define CP_COMMIT() asm volatile("cp.async.commit_group;")
#define CP_WAIT1()  asm volatile("cp.async.wait_group 1;")
#define CP_WAIT0()  asm volatile("cp.async.wait_group 0;")

#define MMA_F16(acc, a0, a1, a2, a3, b0, b1)                                \
    asm volatile(                                                           \
        "mma.sync.aligned.m16n8k16.row.col.f32.f16.f16.f32 "                \
        "{%0,%1,%2,%3}, {%4,%5,%6,%7}, {%8,%9}, {%0,%1,%2,%3};"             \
        : "+f"(acc[0]), "+f"(acc[1]), "+f"(acc[2]), "+f"(acc[3])            \
        : "r"(a0), "r"(a1), "r"(a2), "r"(a3), "r"(b0), "r"(b1))

// gemm stage stride: 128 rows x 40 halves
#define STG 5120
// kv transpose tile stride (halves): 272 bytes, 16B-aligned rows for ldmatrix
#define KVS 136
// spike (0/1) -> fp16 bit pattern
#define H1(u) ((unsigned short)((u) * 0x3C00u))

// ---------------------------------------------------------------------------
// fp32 -> fp16 convert (query, W_in, W_out)
// ---------------------------------------------------------------------------
__global__ __launch_bounds__(256) void conv_kernel(
    const float* __restrict__ src, __half* __restrict__ d0)
{
    size_t i4 = ((size_t)blockIdx.x * 256 + threadIdx.x) * 4;
    float4 v = *(const float4*)(src + i4);
    __half h[4] = {__float2half_rn(v.x), __float2half_rn(v.y),
                   __float2half_rn(v.z), __float2half_rn(v.w)};
    *(uint2*)(d0 + i4) = *(uint2*)h;
}

__global__ void zero_flag_kernel() { g_nflag = 0u; }

// ---------------------------------------------------------------------------
// GEMM1 fast path: proj = q @ W_in^T + bias, single pure-fp16 mma pass.
// Fast-path error (sigma ~2.1e-4, max ~1.2e-3) repaired by exact fixup
// (DELTA = 2.5e-3). ldmatrix + cp.async 2-stage pipeline. smem 40 KB.
// ---------------------------------------------------------------------------
__global__ __launch_bounds__(256) void gemm1_fast_kernel(
    const float* __restrict__ bias)
{
    extern __shared__ __half dsm[];
    __half* A0s = dsm;              // [2][128][40]
    __half* B0s = dsm + 2*STG;

    const int bm = blockIdx.y * 128;
    const int bn = blockIdx.x * 128;
    const int tid  = threadIdx.x;
    const int wid  = tid >> 5;
    const int lane = tid & 31;
    const int wm = wid >> 1;
    const int wn = wid & 1;
    const int lr = lane >> 2;
    const int lc = (lane & 3) * 2;

    const int a_r = lane & 15, a_k = (lane >> 4) * 8;
    const int b_r = (lane & 7) + ((lane >> 4) << 3);
    const int b_k = ((lane >> 3) & 1) * 8;

    float acc[2][8][4];
    #pragma unroll
    for (int mi = 0; mi < 2; mi++)
        #pragma unroll
        for (int ni = 0; ni < 8; ni++)
            #pragma unroll
            for (int r = 0; r < 4; r++) acc[mi][ni][r] = 0.f;

    auto load_stage = [&](int s, int k0) {
        #pragma unroll
        for (int i = tid; i < 512; i += 256) {
            int row = i >> 2, c8 = (i & 3) << 3;
            int so = s*STG + row*40 + c8;
            cp16(A0s + so, g_a0 + (size_t)(bm + row) * Ee + k0 + c8);
            cp16(B0s + so, g_w0 + (size_t)(bn + row) * Ee + k0 + c8);
        }
    };

    load_stage(0, 0);
    CP_COMMIT();

    const int NT = Ee / 32;   // 16
    for (int it = 0; it < NT; it++) {
        if (it + 1 < NT) {
            load_stage((it + 1) & 1, (it + 1) * 32);
            CP_COMMIT();
            CP_WAIT1();
        } else {
            CP_WAIT0();
        }
        __syncthreads();

        const int sb = (it & 1) * STG;
        #pragma unroll
        for (int kk = 0; kk < 32; kk += 16) {
            uint32_t a0[2][4];
            #pragma unroll
            for (int mi = 0; mi < 2; mi++) {
                int rb = wm*32 + mi*16;
                ldsm_x4(a0[mi][0], a0[mi][1], a0[mi][2], a0[mi][3],
                        A0s + sb + (rb + a_r)*40 + kk + a_k);
            }
            uint32_t bh[8][2];
            #pragma unroll
            for (int nb = 0; nb < 4; nb++) {
                int n0 = wn*64 + nb*16;
                ldsm_x4(bh[nb*2][0], bh[nb*2][1], bh[nb*2+1][0], bh[nb*2+1][1],
                        B0s + sb + (n0 + b_r)*40 + kk + b_k);
            }
            #pragma unroll
            for (int ni = 0; ni < 8; ni++) {
                #pragma unroll
                for (int mi = 0; mi < 2; mi++) {
                    MMA_F16(acc[mi][ni], a0[mi][0], a0[mi][1], a0[mi][2],
                            a0[mi][3], bh[ni][0], bh[ni][1]);
                }
            }
        }
        __syncthreads();
    }

    #pragma unroll
    for (int mi = 0; mi < 2; mi++) {
        #pragma unroll
        for (int ni = 0; ni < 8; ni++) {
            int col = bn + wn*64 + ni*8 + lc;
            float b0 = bias[col], b1 = bias[col + 1];
            int row0 = bm + wm*32 + mi*16 + lr;
            *(float2*)(g_proj + (size_t)row0 * N3 + col) =
                make_float2(acc[mi][ni][0] + b0, acc[mi][ni][1] + b1);
            *(float2*)(g_proj + (size_t)(row0 + 8) * N3 + col) =
                make_float2(acc[mi][ni][2] + b0, acc[mi][ni][3] + b1);
        }
    }
}

// ---------------------------------------------------------------------------
// LIF over t on fast proj; flag neurons with any |h - 1| < DELTA.
// ---------------------------------------------------------------------------
__global__ __launch_bounds__(256) void lif_flag_kernel()
{
    size_t i = (size_t)blockIdx.x * 256 + threadIdx.x;   // over LB*N3
    float v = 0.f;
    bool flag = false;
    #pragma unroll
    for (int t = 0; t < Tt; t++) {
        float x = g_proj[(size_t)t * LB * N3 + i];
        float h = v + (x - v) * 0.5f;
        flag |= fabsf(h - 1.0f) < DELTA;
        bool s = (h - 1.0f) >= 0.f;
        g_spk[(size_t)t * LB * N3 + i] = s ? 1 : 0;
        v = s ? 0.f : h;
    }
    if (flag) {
        unsigned int p = atomicAdd(&g_nflag, 1u);
        if (p < FIX_CAP) g_list[p] = (unsigned int)i;
    }
}

// ---------------------------------------------------------------------------
// Exact fixup: sequential-K fp32 FMA (bitwise-reference order).
// ---------------------------------------------------------------------------
__global__ __launch_bounds__(256) void fixup_kernel(
    const float* __restrict__ Q, const float* __restrict__ W,
    const float* __restrict__ bias)
{
    unsigned int tid = blockIdx.x * 256 + threadIdx.x;
    unsigned int n = g_nflag; if (n > FIX_CAP) n = FIX_CAP;
    if (tid >= n) return;
    unsigned int i = g_list[tid];
    int lb = i / N3;
    int f  = i - lb * N3;

    const float* wr = W + (size_t)f * Ee;
    float acc[4] = {0.f, 0.f, 0.f, 0.f};
    for (int k = 0; k < Ee; k += 4) {
        float4 wv = *(const float4*)(wr + k);
        #pragma unroll
        for (int t = 0; t < Tt; t++) {
            const float* qr = Q + ((size_t)t * LB + lb) * Ee + k;
            float4 qv = *(const float4*)qr;
            acc[t] = fmaf(qv.x, wv.x, acc[t]);
            acc[t] = fmaf(qv.y, wv.y, acc[t]);
            acc[t] = fmaf(qv.z, wv.z, acc[t]);
            acc[t] = fmaf(qv.w, wv.w, acc[t]);
        }
    }
    float b = bias[f];
    float v = 0.f;
    #pragma unroll
    for (int t = 0; t < Tt; t++) {
        float x = acc[t] + b;
        float h = v + (x - v) * 0.5f;
        bool s = (h - 1.0f) >= 0.f;
        g_spk[(size_t)t * LB * N3 + i] = s ? 1 : 0;
        v = s ? 0.f : h;
    }
}

// ---------------------------------------------------------------------------
// kv attention on tensor cores: attnT[t,n][e][d] = sum_l v[l,e] * k[l,d].
// (Validated R9: exact integer counts, no atomics.)
// ---------------------------------------------------------------------------
__global__ __launch_bounds__(256) void kv_attn_kernel()
{
    const int n = blockIdx.x, t = blockIdx.y;
    const int b = n >> 3, h = n & 7;
    __shared__ __half vT[64 * KVS];   // [e][l]
    __shared__ __half kT[64 * KVS];   // [d][l]

    const int tid  = threadIdx.x;
    const int wid  = tid >> 5;
    const int lane = tid & 31;
    const int e0 = (wid >> 1) * 16;
    const int d0 = (wid & 1) * 32;
    const int lr = lane >> 2;
    const int lc = (lane & 3) * 2;

    const int a_r = lane & 15, a_k = (lane >> 4) * 8;
    const int b_r = (lane & 7) + ((lane >> 4) << 3);
    const int b_k = ((lane >> 3) & 1) * 8;

    float acc[4][4];
    #pragma unroll
    for (int ni = 0; ni < 4; ni++)
        #pragma unroll
        for (int r = 0; r < 4; r++) acc[ni][r] = 0.f;

    for (int l0 = 0; l0 < Ll; l0 += 128) {
        __syncthreads();
        for (int i = tid; i < 2048; i += 256) {
            int ll = i >> 4, d4 = (i & 15) << 2;
            size_t base = ((size_t)t * LB + (size_t)(l0 + ll) * Bb + b) * N3
                          + h * 64 + d4;
            uchar4 kc = *(const uchar4*)(g_spk + base + 512);
            uchar4 vc = *(const uchar4*)(g_spk + base + 1024);
            kT[(d4+0)*KVS + ll] = __ushort_as_half(H1(kc.x));
            kT[(d4+1)*KVS + ll] = __ushort_as_half(H1(kc.y));
            kT[(d4+2)*KVS + ll] = __ushort_as_half(H1(kc.z));
            kT[(d4+3)*KVS + ll] = __ushort_as_half(H1(kc.w));
            vT[(d4+0)*KVS + ll] = __ushort_as_half(H1(vc.x));
            vT[(d4+1)*KVS + ll] = __ushort_as_half(H1(vc.y));
            vT[(d4+2)*KVS + ll] = __ushort_as_half(H1(vc.z));
            vT[(d4+3)*KVS + ll] = __ushort_as_half(H1(vc.w));
        }
        __syncthreads();

        #pragma unroll
        for (int kk = 0; kk < 128; kk += 16) {
            uint32_t a[4];
            ldsm_x4(a[0], a[1], a[2], a[3], &vT[(e0 + a_r)*KVS + kk + a_k]);
            uint32_t bt[4][2];
            #pragma unroll
            for (int nb = 0; nb < 2; nb++)
                ldsm_x4(bt[nb*2][0], bt[nb*2][1], bt[nb*2+1][0], bt[nb*2+1][1],
                        &kT[(d0 + nb*16 + b_r)*KVS + kk + b_k]);
            #pragma unroll
            for (int ni = 0; ni < 4; ni++)
                MMA_F16(acc[ni], a[0], a[1], a[2], a[3], bt[ni][0], bt[ni][1]);
        }
    }

    __half* ap = g_attn + (size_t)(t * 64 + n) * 4096;
    #pragma unroll
    for (int ni = 0; ni < 4; ni++) {
        int d = d0 + ni*8 + lc;
        *(__half2*)(ap + (e0 + lr) * 64 + d) =
            __floats2half2_rn(acc[ni][0], acc[ni][1]);
        *(__half2*)(ap + (e0 + lr + 8) * 64 + d) =
            __floats2half2_rn(acc[ni][2], acc[ni][3]);
    }
}

// ---------------------------------------------------------------------------
// q @ attn on tensor cores + fused LIF(0.5). (Validated R9: exact.)
// ---------------------------------------------------------------------------
__global__ __launch_bounds__(256) void qattn_lif_kernel()
{
    const int n = blockIdx.y, lt = blockIdx.x;
    const int b = n >> 3, h = n & 7;
    __shared__ __half qs[128][72];
    __shared__ __half at[64][72];

    const int tid  = threadIdx.x;
    const int wid  = tid >> 5;
    const int lane = tid & 31;
    const int wm = wid >> 1;
    const int wn = wid & 1;
    const int lr = lane >> 2;
    const int lc = (lane & 3) * 2;

    const int a_r = lane & 15, a_k = (lane >> 4) * 8;
    const int b_r = (lane & 7) + ((lane >> 4) << 3);
    const int b_k = ((lane >> 3) & 1) * 8;

    float vmem[2][4][4];
    #pragma unroll
    for (int mi = 0; mi < 2; mi++)
        #pragma unroll
        for (int ni = 0; ni < 4; ni++)
            #pragma unroll
            for (int r = 0; r < 4; r++) vmem[mi][ni][r] = 0.f;

    for (int t = 0; t < Tt; t++) {
        __syncthreads();
        for (int i = tid; i < 2048; i += 256) {
            int ll = i >> 4, d4 = (i & 15) << 2;
            size_t base = ((size_t)t * LB + (size_t)(lt*128 + ll) * Bb + b) * N3
                          + h * 64 + d4;
            uchar4 qc = *(const uchar4*)(g_spk + base);
            unsigned short hh[4] = {H1(qc.x), H1(qc.y), H1(qc.z), H1(qc.w)};
            *(uint2*)&qs[ll][d4] = *(uint2*)hh;
        }
        for (int i = tid; i < 512; i += 256) {
            int row = i >> 3, c8 = (i & 7) << 3;
            *(uint4*)&at[row][c8] =
                *(const uint4*)(g_attn + (size_t)(t*64 + n) * 4096 + row*64 + c8);
        }
        __syncthreads();

        float acc[2][4][4];
        #pragma unroll
        for (int mi = 0; mi < 2; mi++)
            #pragma unroll
            for (int ni = 0; ni < 4; ni++)
                #pragma unroll
                for (int r = 0; r < 4; r++) acc[mi][ni][r] = 0.f;

        #pragma unroll
        for (int kk = 0; kk < 64; kk += 16) {
            uint32_t a[2][4];
            #pragma unroll
            for (int mi = 0; mi < 2; mi++)
                ldsm_x4(a[mi][0], a[mi][1], a[mi][2], a[mi][3],
                        &qs[wm*32 + mi*16 + a_r][kk + a_k]);
            uint32_t bt[4][2];
            #pragma unroll
            for (int nb = 0; nb < 2; nb++)
                ldsm_x4(bt[nb*2][0], bt[nb*2][1], bt[nb*2+1][0], bt[nb*2+1][1],
                        &at[wn*32 + nb*16 + b_r][kk + b_k]);
            #pragma unroll
            for (int ni = 0; ni < 4; ni++)
                #pragma unroll
                for (int mi = 0; mi < 2; mi++)
                    MMA_F16(acc[mi][ni], a[mi][0], a[mi][1], a[mi][2], a[mi][3],
                            bt[ni][0], bt[ni][1]);
        }

        #pragma unroll
        for (int mi = 0; mi < 2; mi++) {
            #pragma unroll
            for (int ni = 0; ni < 4; ni++) {
                int e = wn*32 + ni*8 + lc;
                #pragma unroll
                for (int rp = 0; rp < 2; rp++) {
                    int l = lt*128 + wm*32 + mi*16 + lr + rp*8;
                    unsigned short sp[2];
                    #pragma unroll
                    for (int c = 0; c < 2; c++) {
                        int r = rp*2 + c;
                        float x = acc[mi][ni][r] * 0.125f;
                        float v = vmem[mi][ni][r];
                        float hh = v + (x - v) * 0.5f;
                        bool s = (hh - 0.5f) >= 0.f;
                        sp[c] = s ? 0x3C00 : 0;
                        vmem[mi][ni][r] = s ? 0.f : hh;
                    }
                    *(uint32_t*)(g_s2 + (((size_t)t * Ll + l) * Bb + b) * Ee
                                 + h * 64 + e) = *(uint32_t*)sp;
                }
            }
        }
    }
}

// ---------------------------------------------------------------------------
// GEMM5: out = s2 @ W_out^T + bias, single pure-fp16 pass.
// Dropped w_lo term: norm-relative error ~2.8e-4 (vs 1e-3 threshold).
// ---------------------------------------------------------------------------
__global__ __launch_bounds__(256) void gemm5_mma_kernel(
    const float* __restrict__ bias, float* __restrict__ C)
{
    extern __shared__ __half dsm[];
    __half* As  = dsm;              // [2][128][40]
    __half* Bhi = dsm + 2*STG;

    const int bm = blockIdx.y * 128;
    const int bn = blockIdx.x * 128;
    const int tid  = threadIdx.x;
    const int wid  = tid >> 5;
    const int lane = tid & 31;
    const int wm = wid >> 1;
    const int wn = wid & 1;
    const int lr = lane >> 2;
    const int lc = (lane & 3) * 2;

    const int a_r = lane & 15, a_k = (lane >> 4) * 8;
    const int b_r = (lane & 7) + ((lane >> 4) << 3);
    const int b_k = ((lane >> 3) & 1) * 8;

    float acc[2][8][4];
    #pragma unroll
    for (int mi = 0; mi < 2; mi++)
        #pragma unroll
        for (int ni = 0; ni < 8; ni++)
            #pragma unroll
            for (int r = 0; r < 4; r++) acc[mi][ni][r] = 0.f;

    auto load_stage = [&](int s, int k0) {
        #pragma unroll
        for (int i = tid; i < 512; i += 256) {
            int row = i >> 2, c8 = (i & 3) << 3;
            int so = s*STG + row*40 + c8;
            cp16(As + so, g_s2 + (size_t)(bm + row) * Ee + k0 + c8);
            cp16(Bhi + so, g_whi + (size_t)(bn + row) * Ee + k0 + c8);
        }
    };

    load_stage(0, 0);
    CP_COMMIT();

    const int NT = Ee / 32;
    for (int it = 0; it < NT; it++) {
        if (it + 1 < NT) {
            load_stage((it + 1) & 1, (it + 1) * 32);
            CP_COMMIT();
            CP_WAIT1();
        } else {
            CP_WAIT0();
        }
        __syncthreads();

        const int sb = (it & 1) * STG;
        #pragma unroll
        for (int kk = 0; kk < 32; kk += 16) {
            uint32_t a[2][4];
            #pragma unroll
            for (int mi = 0; mi < 2; mi++) {
                int rb = wm*32 + mi*16;
                ldsm_x4(a[mi][0], a[mi][1], a[mi][2], a[mi][3],
                        As + sb + (rb + a_r)*40 + kk + a_k);
            }
            uint32_t bh[8][2];
            #pragma unroll
            for (int nb = 0; nb < 4; nb++) {
                int n0 = wn*64 + nb*16;
                ldsm_x4(bh[nb*2][0], bh[nb*2][1], bh[nb*2+1][0], bh[nb*2+1][1],
                        Bhi + sb + (n0 + b_r)*40 + kk + b_k);
            }
            #pragma unroll
            for (int ni = 0; ni < 8; ni++) {
                #pragma unroll
                for (int mi = 0; mi < 2; mi++) {
                    MMA_F16(acc[mi][ni], a[mi][0], a[mi][1], a[mi][2], a[mi][3],
                            bh[ni][0], bh[ni][1]);
                }
            }
        }
        __syncthreads();
    }

    #pragma unroll
    for (int mi = 0; mi < 2; mi++) {
        #pragma unroll
        for (int ni = 0; ni < 8; ni++) {
            int col = bn + wn*64 + ni*8 + lc;
            float b0 = bias[col], b1 = bias[col + 1];
            int row0 = bm + wm*32 + mi*16 + lr;
            *(float2*)(C + (size_t)row0 * Ee + col) =
                make_float2(acc[mi][ni][0] + b0, acc[mi][ni][1] + b1);
            *(float2*)(C + (size_t)(row0 + 8) * Ee + col) =
                make_float2(acc[mi][ni][2] + b0, acc[mi][ni][3] + b1);
        }
    }
}

// ---------------------------------------------------------------------------
extern "C" void kernel_launch(void* const* d_in, const int* in_sizes, int n_in,
                              void* d_out, int out_size)
{
    const float* query = (const float*)d_in[0];   // (T,L,B,E)
    const float* w_in  = (const float*)d_in[1];   // (3E, E)
    const float* b_in  = (const float*)d_in[2];   // (3E)
    const float* w_out = (const float*)d_in[3];   // (E, E)
    const float* b_out = (const float*)d_in[4];   // (E)
    float* out = (float*)d_out;                   // (T,L,B,E)

    void *p_a0, *p_w0, *p_whi;
    cudaGetSymbolAddress(&p_a0, g_a0);
    cudaGetSymbolAddress(&p_w0, g_w0);
    cudaGetSymbolAddress(&p_whi, g_whi);

    // 0) zero flag counter + fp16 converts
    zero_flag_kernel<<<1, 1>>>();
    conv_kernel<<<((size_t)Mm * Ee / 4) / 256, 256>>>(query, (__half*)p_a0);
    conv_kernel<<<((size_t)N3 * Ee / 4) / 256, 256>>>(w_in, (__half*)p_w0);
    conv_kernel<<<((size_t)Ee * Ee / 4) / 256, 256>>>(w_out, (__half*)p_whi);

    // 1) fast proj on tensor cores (single pure-fp16 pass)
    const int SM1 = 4 * STG * (int)sizeof(__half);   // 40 KB
    cudaFuncSetAttribute(gemm1_fast_kernel,
                         cudaFuncAttributeMaxDynamicSharedMemorySize, SM1);
    gemm1_fast_kernel<<<dim3(N3 / 128, Mm / 128), 256, SM1>>>(b_in);

    // 2) LIF + flag marginal neurons (DELTA=2.5e-3), then exact fixup
    lif_flag_kernel<<<((size_t)LB * N3) / 256, 256>>>();
    fixup_kernel<<<FIX_CAP / 256, 256>>>(query, w_in, b_in);

    // 3) attnT = v^T k per (t, head) on tensor cores
    kv_attn_kernel<<<dim3(64, Tt), 256>>>();

    // 4) out = q @ attn * 0.125 -> LIF(0.5) -> s2 spikes, tensor cores
    qattn_lif_kernel<<<dim3(Ll / 128, 64), 256>>>();

    // 5) final = s2 @ W_out^T + b_out, single fp16 pass
    const int SM5 = 4 * STG * (int)sizeof(__half);   // 40 KB
    cudaFuncSetAttribute(gemm5_mma_kernel,
                         cudaFuncAttributeMaxDynamicSharedMemorySize, SM5);
    gemm5_mma_kernel<<<dim3(Ee / 128, Mm / 128), 256, SM5>>>(b_out, out);
}

// round 14
// speedup vs baseline: 1.7975x; 1.2127x over previous
#include <cuda_runtime.h>
#include <cuda_fp16.h>
#include <cstdint>

// Problem dims (fixed)
#define Tt 4
#define Ll 2048
#define Bb 8
#define Ee 512
#define LB (Ll*Bb)        // 16384
#define Mm (Tt*LB)        // 65536
#define N3 (3*Ee)         // 1536
#define FIX_CAP (1u<<20)
#define DELTA 2.5e-3f

// Scratch (device globals, allocation-free rule)
static __device__ __half   g_a0  [(size_t)Mm * Ee];   // query (fp16)
static __device__ __half   g_w0  [N3 * Ee];           // W_in (fp16)
static __device__ uint8_t  g_spk [(size_t)Mm * N3];   // qkv spikes
static __device__ __half   g_attn[Tt * 64 * 64 * 64]; // attn^T counts (exact fp16)
static __device__ __half   g_s2  [(size_t)Mm * Ee];   // s2 spikes (fp16 0/1)
static __device__ __half   g_whi [Ee * Ee];           // W_out (fp16)
static __device__ unsigned int g_nflag;
static __device__ unsigned int g_list[FIX_CAP];

__device__ __forceinline__ void ldsm_x4(uint32_t& r0, uint32_t& r1,
                                        uint32_t& r2, uint32_t& r3,
                                        const void* p)
{
    uint32_t a = (uint32_t)__cvta_generic_to_shared(p);
    asm volatile("ldmatrix.sync.aligned.m8n8.x4.shared.b16 {%0,%1,%2,%3}, [%4];"
                 : "=r"(r0), "=r"(r1), "=r"(r2), "=r"(r3) : "r"(a));
}

__device__ __forceinline__ void cp16(void* dst, const void* src)
{
    uint32_t d = (uint32_t)__cvta_generic_to_shared(dst);
    asm volatile("cp.async.cg.shared.global [%0], [%1], 16;" :: "r"(d), "l"(src));
}
#define CP_COMMIT() asm volatile("cp.async.commit_group;")
#define CP_WAIT1()  asm volatile("cp.async.wait_group 1;")
#define CP_WAIT0()  asm volatile("cp.async.wait_group 0;")

#define MMA_F16(acc, a0, a1, a2, a3, b0, b1)                                \
    asm volatile(                                                           \
        "mma.sync.aligned.m16n8k16.row.col.f32.f16.f16.f32 "                \
        "{%0,%1,%2,%3}, {%4,%5,%6,%7}, {%8,%9}, {%0,%1,%2,%3};"             \
        : "+f"(acc[0]), "+f"(acc[1]), "+f"(acc[2]), "+f"(acc[3])            \
        : "r"(a0), "r"(a1), "r"(a2), "r"(a3), "r"(b0), "r"(b1))

// gemm stage stride: 128 rows x 40 halves
#define STG 5120
// epilogue fp32 tile stride (floats): conflict-free, 128*132*4 = 66 KB
#define VST 132
// kv transpose tile stride (halves): 272 bytes, 16B-aligned rows
#define KVS 136
// spike (0/1) -> fp16 bit pattern
#define H1(u) ((unsigned short)((u) * 0x3C00u))

// ---------------------------------------------------------------------------
// fp32 -> fp16 convert (query, W_in, W_out)
// ---------------------------------------------------------------------------
__global__ __launch_bounds__(256) void conv_kernel(
    const float* __restrict__ src, __half* __restrict__ d0)
{
    size_t i4 = ((size_t)blockIdx.x * 256 + threadIdx.x) * 4;
    float4 v = *(const float4*)(src + i4);
    __half h[4] = {__float2half_rn(v.x), __float2half_rn(v.y),
                   __float2half_rn(v.z), __float2half_rn(v.w)};
    *(uint2*)(d0 + i4) = *(uint2*)h;
}

__global__ void zero_flag_kernel() { g_nflag = 0u; }

// ---------------------------------------------------------------------------
// Fused GEMM1 + LIF: tile rows are t-interleaved (row r <-> lb=bm32+(r>>2),
// t=r&3), so all 4 timesteps of a neuron live in one CTA. Single pure-fp16
// mma pass (error repaired by fixup, DELTA=2.5e-3). Epilogue stages acc+bias
// in smem (reusing pipeline smem after final sync), then runs the LIF scan,
// flags marginal neurons, writes uint8 spikes. No g_proj round-trip.
// Grid (N3/128, LB/32); loop structure identical to the R13 kernel.
// ---------------------------------------------------------------------------
__global__ __launch_bounds__(256) void gemm1_lif_kernel(
    const float* __restrict__ bias)
{
    extern __shared__ __half dsm[];
    __half* A0s = dsm;              // [2][128][40] (pipeline phase)
    __half* B0s = dsm + 2*STG;
    float*  vsm = (float*)dsm;      // [128][VST]  (epilogue phase, reuse)

    const int bn   = blockIdx.x * 128;   // f tile
    const int bm32 = blockIdx.y * 32;    // lb tile (32 lbs x 4 t = 128 rows)
    const int tid  = threadIdx.x;
    const int wid  = tid >> 5;
    const int lane = tid & 31;
    const int wm = wid >> 1;
    const int wn = wid & 1;
    const int lr = lane >> 2;
    const int lc = (lane & 3) * 2;

    const int a_r = lane & 15, a_k = (lane >> 4) * 8;
    const int b_r = (lane & 7) + ((lane >> 4) << 3);
    const int b_k = ((lane >> 3) & 1) * 8;

    // bias cache for this thread's 16 columns
    float bc[8][2];
    #pragma unroll
    for (int ni = 0; ni < 8; ni++) {
        int col = bn + wn*64 + ni*8 + lc;
        bc[ni][0] = bias[col];
        bc[ni][1] = bias[col + 1];
    }

    float acc[2][8][4];
    #pragma unroll
    for (int mi = 0; mi < 2; mi++)
        #pragma unroll
        for (int ni = 0; ni < 8; ni++)
            #pragma unroll
            for (int r = 0; r < 4; r++) acc[mi][ni][r] = 0.f;

    auto load_stage = [&](int s, int k0) {
        #pragma unroll
        for (int i = tid; i < 512; i += 256) {
            int row = i >> 2, c8 = (i & 3) << 3;
            int so = s*STG + row*40 + c8;
            int lb = bm32 + (row >> 2);
            int t  = row & 3;
            cp16(A0s + so, g_a0 + ((size_t)t * LB + lb) * Ee + k0 + c8);
            cp16(B0s + so, g_w0 + (size_t)(bn + row) * Ee + k0 + c8);
        }
    };

    load_stage(0, 0);
    CP_COMMIT();

    const int NT = Ee / 32;   // 16
    for (int it = 0; it < NT; it++) {
        if (it + 1 < NT) {
            load_stage((it + 1) & 1, (it + 1) * 32);
            CP_COMMIT();
            CP_WAIT1();
        } else {
            CP_WAIT0();
        }
        __syncthreads();

        const int sb = (it & 1) * STG;
        #pragma unroll
        for (int kk = 0; kk < 32; kk += 16) {
            uint32_t a0[2][4];
            #pragma unroll
            for (int mi = 0; mi < 2; mi++) {
                int rb = wm*32 + mi*16;
                ldsm_x4(a0[mi][0], a0[mi][1], a0[mi][2], a0[mi][3],
                        A0s + sb + (rb + a_r)*40 + kk + a_k);
            }
            uint32_t bh[8][2];
            #pragma unroll
            for (int nb = 0; nb < 4; nb++) {
                int n0 = wn*64 + nb*16;
                ldsm_x4(bh[nb*2][0], bh[nb*2][1], bh[nb*2+1][0], bh[nb*2+1][1],
                        B0s + sb + (n0 + b_r)*40 + kk + b_k);
            }
            #pragma unroll
            for (int ni = 0; ni < 8; ni++) {
                #pragma unroll
                for (int mi = 0; mi < 2; mi++) {
                    MMA_F16(acc[mi][ni], a0[mi][0], a0[mi][1], a0[mi][2],
                            a0[mi][3], bh[ni][0], bh[ni][1]);
                }
            }
        }
        __syncthreads();
    }

    // Phase 1: stage acc+bias into smem fp32 tile (pipeline smem now free)
    #pragma unroll
    for (int mi = 0; mi < 2; mi++) {
        #pragma unroll
        for (int ni = 0; ni < 8; ni++) {
            #pragma unroll
            for (int rp = 0; rp < 2; rp++) {
                int row = wm*32 + mi*16 + lr + rp*8;
                int col = wn*64 + ni*8 + lc;
                vsm[row*VST + col]     = acc[mi][ni][rp*2]     + bc[ni][0];
                vsm[row*VST + col + 1] = acc[mi][ni][rp*2 + 1] + bc[ni][1];
            }
        }
    }
    __syncthreads();

    // Phase 2: LIF scan per neuron (lb_local, f); rows lb_local*4 + t
    for (int j = tid; j < 4096; j += 256) {
        int f   = j & 127;
        int lbl = j >> 7;
        float v = 0.f;
        bool flag = false;
        #pragma unroll
        for (int t = 0; t < Tt; t++) {
            float x = vsm[(lbl*4 + t)*VST + f];
            float h = v + (x - v) * 0.5f;
            flag |= fabsf(h - 1.0f) < DELTA;
            bool s = (h - 1.0f) >= 0.f;
            g_spk[(size_t)t * LB * N3 + (size_t)(bm32 + lbl) * N3 + bn + f]
                = s ? 1 : 0;
            v = s ? 0.f : h;
        }
        if (flag) {
            unsigned int p = atomicAdd(&g_nflag, 1u);
            if (p < FIX_CAP)
                g_list[p] = (unsigned int)((size_t)(bm32 + lbl) * N3 + bn + f);
        }
    }
}

// ---------------------------------------------------------------------------
// Exact fixup: sequential-K fp32 FMA (bitwise-reference order).
// ---------------------------------------------------------------------------
__global__ __launch_bounds__(256) void fixup_kernel(
    const float* __restrict__ Q, const float* __restrict__ W,
    const float* __restrict__ bias)
{
    unsigned int tid = blockIdx.x * 256 + threadIdx.x;
    unsigned int n = g_nflag; if (n > FIX_CAP) n = FIX_CAP;
    if (tid >= n) return;
    unsigned int i = g_list[tid];
    int lb = i / N3;
    int f  = i - lb * N3;

    const float* wr = W + (size_t)f * Ee;
    float acc[4] = {0.f, 0.f, 0.f, 0.f};
    for (int k = 0; k < Ee; k += 4) {
        float4 wv = *(const float4*)(wr + k);
        #pragma unroll
        for (int t = 0; t < Tt; t++) {
            const float* qr = Q + ((size_t)t * LB + lb) * Ee + k;
            float4 qv = *(const float4*)qr;
            acc[t] = fmaf(qv.x, wv.x, acc[t]);
            acc[t] = fmaf(qv.y, wv.y, acc[t]);
            acc[t] = fmaf(qv.z, wv.z, acc[t]);
            acc[t] = fmaf(qv.w, wv.w, acc[t]);
        }
    }
    float b = bias[f];
    float v = 0.f;
    #pragma unroll
    for (int t = 0; t < Tt; t++) {
        float x = acc[t] + b;
        float h = v + (x - v) * 0.5f;
        bool s = (h - 1.0f) >= 0.f;
        g_spk[(size_t)t * LB * N3 + i] = s ? 1 : 0;
        v = s ? 0.f : h;
    }
}

// ---------------------------------------------------------------------------
// kv attention on tensor cores: attnT[t,n][e][d] = sum_l v[l,e] * k[l,d].
// (Validated R9: exact integer counts, no atomics.)
// ---------------------------------------------------------------------------
__global__ __launch_bounds__(256) void kv_attn_kernel()
{
    const int n = blockIdx.x, t = blockIdx.y;
    const int b = n >> 3, h = n & 7;
    __shared__ __half vT[64 * KVS];   // [e][l]
    __shared__ __half kT[64 * KVS];   // [d][l]

    const int tid  = threadIdx.x;
    const int wid  = tid >> 5;
    const int lane = tid & 31;
    const int e0 = (wid >> 1) * 16;
    const int d0 = (wid & 1) * 32;
    const int lr = lane >> 2;
    const int lc = (lane & 3) * 2;

    const int a_r = lane & 15, a_k = (lane >> 4) * 8;
    const int b_r = (lane & 7) + ((lane >> 4) << 3);
    const int b_k = ((lane >> 3) & 1) * 8;

    float acc[4][4];
    #pragma unroll
    for (int ni = 0; ni < 4; ni++)
        #pragma unroll
        for (int r = 0; r < 4; r++) acc[ni][r] = 0.f;

    for (int l0 = 0; l0 < Ll; l0 += 128) {
        __syncthreads();
        for (int i = tid; i < 2048; i += 256) {
            int ll = i >> 4, d4 = (i & 15) << 2;
            size_t base = ((size_t)t * LB + (size_t)(l0 + ll) * Bb + b) * N3
                          + h * 64 + d4;
            uchar4 kc = *(const uchar4*)(g_spk + base + 512);
            uchar4 vc = *(const uchar4*)(g_spk + base + 1024);
            kT[(d4+0)*KVS + ll] = __ushort_as_half(H1(kc.x));
            kT[(d4+1)*KVS + ll] = __ushort_as_half(H1(kc.y));
            kT[(d4+2)*KVS + ll] = __ushort_as_half(H1(kc.z));
            kT[(d4+3)*KVS + ll] = __ushort_as_half(H1(kc.w));
            vT[(d4+0)*KVS + ll] = __ushort_as_half(H1(vc.x));
            vT[(d4+1)*KVS + ll] = __ushort_as_half(H1(vc.y));
            vT[(d4+2)*KVS + ll] = __ushort_as_half(H1(vc.z));
            vT[(d4+3)*KVS + ll] = __ushort_as_half(H1(vc.w));
        }
        __syncthreads();

        #pragma unroll
        for (int kk = 0; kk < 128; kk += 16) {
            uint32_t a[4];
            ldsm_x4(a[0], a[1], a[2], a[3], &vT[(e0 + a_r)*KVS + kk + a_k]);
            uint32_t bt[4][2];
            #pragma unroll
            for (int nb = 0; nb < 2; nb++)
                ldsm_x4(bt[nb*2][0], bt[nb*2][1], bt[nb*2+1][0], bt[nb*2+1][1],
                        &kT[(d0 + nb*16 + b_r)*KVS + kk + b_k]);
            #pragma unroll
            for (int ni = 0; ni < 4; ni++)
                MMA_F16(acc[ni], a[0], a[1], a[2], a[3], bt[ni][0], bt[ni][1]);
        }
    }

    __half* ap = g_attn + (size_t)(t * 64 + n) * 4096;
    #pragma unroll
    for (int ni = 0; ni < 4; ni++) {
        int d = d0 + ni*8 + lc;
        *(__half2*)(ap + (e0 + lr) * 64 + d) =
            __floats2half2_rn(acc[ni][0], acc[ni][1]);
        *(__half2*)(ap + (e0 + lr + 8) * 64 + d) =
            __floats2half2_rn(acc[ni][2], acc[ni][3]);
    }
}

// ---------------------------------------------------------------------------
// q @ attn on tensor cores + fused LIF(0.5). (Validated R9: exact.)
// ---------------------------------------------------------------------------
__global__ __launch_bounds__(256) void qattn_lif_kernel()
{
    const int n = blockIdx.y, lt = blockIdx.x;
    const int b = n >> 3, h = n & 7;
    __shared__ __half qs[128][72];
    __shared__ __half at[64][72];

    const int tid  = threadIdx.x;
    const int wid  = tid >> 5;
    const int lane = tid & 31;
    const int wm = wid >> 1;
    const int wn = wid & 1;
    const int lr = lane >> 2;
    const int lc = (lane & 3) * 2;

    const int a_r = lane & 15, a_k = (lane >> 4) * 8;
    const int b_r = (lane & 7) + ((lane >> 4) << 3);
    const int b_k = ((lane >> 3) & 1) * 8;

    float vmem[2][4][4];
    #pragma unroll
    for (int mi = 0; mi < 2; mi++)
        #pragma unroll
        for (int ni = 0; ni < 4; ni++)
            #pragma unroll
            for (int r = 0; r < 4; r++) vmem[mi][ni][r] = 0.f;

    for (int t = 0; t < Tt; t++) {
        __syncthreads();
        for (int i = tid; i < 2048; i += 256) {
            int ll = i >> 4, d4 = (i & 15) << 2;
            size_t base = ((size_t)t * LB + (size_t)(lt*128 + ll) * Bb + b) * N3
                          + h * 64 + d4;
            uchar4 qc = *(const uchar4*)(g_spk + base);
            unsigned short hh[4] = {H1(qc.x), H1(qc.y), H1(qc.z), H1(qc.w)};
            *(uint2*)&qs[ll][d4] = *(uint2*)hh;
        }
        for (int i = tid; i < 512; i += 256) {
            int row = i >> 3, c8 = (i & 7) << 3;
            *(uint4*)&at[row][c8] =
                *(const uint4*)(g_attn + (size_t)(t*64 + n) * 4096 + row*64 + c8);
        }
        __syncthreads();

        float acc[2][4][4];
        #pragma unroll
        for (int mi = 0; mi < 2; mi++)
            #pragma unroll
            for (int ni = 0; ni < 4; ni++)
                #pragma unroll
                for (int r = 0; r < 4; r++) acc[mi][ni][r] = 0.f;

        #pragma unroll
        for (int kk = 0; kk < 64; kk += 16) {
            uint32_t a[2][4];
            #pragma unroll
            for (int mi = 0; mi < 2; mi++)
                ldsm_x4(a[mi][0], a[mi][1], a[mi][2], a[mi][3],
                        &qs[wm*32 + mi*16 + a_r][kk + a_k]);
            uint32_t bt[4][2];
            #pragma unroll
            for (int nb = 0; nb < 2; nb++)
                ldsm_x4(bt[nb*2][0], bt[nb*2][1], bt[nb*2+1][0], bt[nb*2+1][1],
                        &at[wn*32 + nb*16 + b_r][kk + b_k]);
            #pragma unroll
            for (int ni = 0; ni < 4; ni++)
                #pragma unroll
                for (int mi = 0; mi < 2; mi++)
                    MMA_F16(acc[mi][ni], a[mi][0], a[mi][1], a[mi][2], a[mi][3],
                            bt[ni][0], bt[ni][1]);
        }

        #pragma unroll
        for (int mi = 0; mi < 2; mi++) {
            #pragma unroll
            for (int ni = 0; ni < 4; ni++) {
                int e = wn*32 + ni*8 + lc;
                #pragma unroll
                for (int rp = 0; rp < 2; rp++) {
                    int l = lt*128 + wm*32 + mi*16 + lr + rp*8;
                    unsigned short sp[2];
                    #pragma unroll
                    for (int c = 0; c < 2; c++) {
                        int r = rp*2 + c;
                        float x = acc[mi][ni][r] * 0.125f;
                        float v = vmem[mi][ni][r];
                        float hh = v + (x - v) * 0.5f;
                        bool s = (hh - 0.5f) >= 0.f;
                        sp[c] = s ? 0x3C00 : 0;
                        vmem[mi][ni][r] = s ? 0.f : hh;
                    }
                    *(uint32_t*)(g_s2 + (((size_t)t * Ll + l) * Bb + b) * Ee
                                 + h * 64 + e) = *(uint32_t*)sp;
                }
            }
        }
    }
}

// ---------------------------------------------------------------------------
// GEMM5: out = s2 @ W_out^T + bias, single pure-fp16 pass. (Validated R13.)
// ---------------------------------------------------------------------------
__global__ __launch_bounds__(256) void gemm5_mma_kernel(
    const float* __restrict__ bias, float* __restrict__ C)
{
    extern __shared__ __half dsm[];
    __half* As  = dsm;              // [2][128][40]
    __half* Bhi = dsm + 2*STG;

    const int bm = blockIdx.y * 128;
    const int bn = blockIdx.x * 128;
    const int tid  = threadIdx.x;
    const int wid  = tid >> 5;
    const int lane = tid & 31;
    const int wm = wid >> 1;
    const int wn = wid & 1;
    const int lr = lane >> 2;
    const int lc = (lane & 3) * 2;

    const int a_r = lane & 15, a_k = (lane >> 4) * 8;
    const int b_r = (lane & 7) + ((lane >> 4) << 3);
    const int b_k = ((lane >> 3) & 1) * 8;

    float acc[2][8][4];
    #pragma unroll
    for (int mi = 0; mi < 2; mi++)
        #pragma unroll
        for (int ni = 0; ni < 8; ni++)
            #pragma unroll
            for (int r = 0; r < 4; r++) acc[mi][ni][r] = 0.f;

    auto load_stage = [&](int s, int k0) {
        #pragma unroll
        for (int i = tid; i < 512; i += 256) {
            int row = i >> 2, c8 = (i & 3) << 3;
            int so = s*STG + row*40 + c8;
            cp16(As + so, g_s2 + (size_t)(bm + row) * Ee + k0 + c8);
            cp16(Bhi + so, g_whi + (size_t)(bn + row) * Ee + k0 + c8);
        }
    };

    load_stage(0, 0);
    CP_COMMIT();

    const int NT = Ee / 32;
    for (int it = 0; it < NT; it++) {
        if (it + 1 < NT) {
            load_stage((it + 1) & 1, (it + 1) * 32);
            CP_COMMIT();
            CP_WAIT1();
        } else {
            CP_WAIT0();
        }
        __syncthreads();

        const int sb = (it & 1) * STG;
        #pragma unroll
        for (int kk = 0; kk < 32; kk += 16) {
            uint32_t a[2][4];
            #pragma unroll
            for (int mi = 0; mi < 2; mi++) {
                int rb = wm*32 + mi*16;
                ldsm_x4(a[mi][0], a[mi][1], a[mi][2], a[mi][3],
                        As + sb + (rb + a_r)*40 + kk + a_k);
            }
            uint32_t bh[8][2];
            #pragma unroll
            for (int nb = 0; nb < 4; nb++) {
                int n0 = wn*64 + nb*16;
                ldsm_x4(bh[nb*2][0], bh[nb*2][1], bh[nb*2+1][0], bh[nb*2+1][1],
                        Bhi + sb + (n0 + b_r)*40 + kk + b_k);
            }
            #pragma unroll
            for (int ni = 0; ni < 8; ni++) {
                #pragma unroll
                for (int mi = 0; mi < 2; mi++) {
                    MMA_F16(acc[mi][ni], a[mi][0], a[mi][1], a[mi][2], a[mi][3],
                            bh[ni][0], bh[ni][1]);
                }
            }
        }
        __syncthreads();
    }

    #pragma unroll
    for (int mi = 0; mi < 2; mi++) {
        #pragma unroll
        for (int ni = 0; ni < 8; ni++) {
            int col = bn + wn*64 + ni*8 + lc;
            float b0 = bias[col], b1 = bias[col + 1];
            int row0 = bm + wm*32 + mi*16 + lr;
            *(float2*)(C + (size_t)row0 * Ee + col) =
                make_float2(acc[mi][ni][0] + b0, acc[mi][ni][1] + b1);
            *(float2*)(C + (size_t)(row0 + 8) * Ee + col) =
                make_float2(acc[mi][ni][2] + b0, acc[mi][ni][3] + b1);
        }
    }
}

// ---------------------------------------------------------------------------
extern "C" void kernel_launch(void* const* d_in, const int* in_sizes, int n_in,
                              void* d_out, int out_size)
{
    const float* query = (const float*)d_in[0];   // (T,L,B,E)
    const float* w_in  = (const float*)d_in[1];   // (3E, E)
    const float* b_in  = (const float*)d_in[2];   // (3E)
    const float* w_out = (const float*)d_in[3];   // (E, E)
    const float* b_out = (const float*)d_in[4];   // (E)
    float* out = (float*)d_out;                   // (T,L,B,E)

    void *p_a0, *p_w0, *p_whi;
    cudaGetSymbolAddress(&p_a0, g_a0);
    cudaGetSymbolAddress(&p_w0, g_w0);
    cudaGetSymbolAddress(&p_whi, g_whi);

    // 0) zero flag counter + fp16 converts
    zero_flag_kernel<<<1, 1>>>();
    conv_kernel<<<((size_t)Mm * Ee / 4) / 256, 256>>>(query, (__half*)p_a0);
    conv_kernel<<<((size_t)N3 * Ee / 4) / 256, 256>>>(w_in, (__half*)p_w0);
    conv_kernel<<<((size_t)Ee * Ee / 4) / 256, 256>>>(w_out, (__half*)p_whi);

    // 1) fused proj + LIF + flag on tensor cores (t-interleaved tiles)
    const int SM1 = 128 * VST * 4;   // 66 KB (>= pipeline 40 KB, reused)
    cudaFuncSetAttribute(gemm1_lif_kernel,
                         cudaFuncAttributeMaxDynamicSharedMemorySize, SM1);
    gemm1_lif_kernel<<<dim3(N3 / 128, LB / 32), 256, SM1>>>(b_in);

    // 2) exact fixup of flagged neurons
    fixup_kernel<<<FIX_CAP / 256, 256>>>(query, w_in, b_in);

    // 3) attnT = v^T k per (t, head) on tensor cores
    kv_attn_kernel<<<dim3(64, Tt), 256>>>();

    // 4) out = q @ attn * 0.125 -> LIF(0.5) -> s2 spikes, tensor cores
    qattn_lif_kernel<<<dim3(Ll / 128, 64), 256>>>();

    // 5) final = s2 @ W_out^T + b_out, single fp16 pass
    const int SM5 = 4 * STG * (int)sizeof(__half);   // 40 KB
    cudaFuncSetAttribute(gemm5_mma_kernel,
                         cudaFuncAttributeMaxDynamicSharedMemorySize, SM5);
    gemm5_mma_kernel<<<dim3(Ee / 128, Mm / 128), 256, SM5>>>(b_out, out);
}

// round 16
// speedup vs baseline: 2.0102x; 1.1183x over previous
#include <cuda_runtime.h>
#include <cuda_fp16.h>
#include <cstdint>

// Problem dims (fixed)
#define Tt 4
#define Ll 2048
#define Bb 8
#define Ee 512
#define LB (Ll*Bb)        // 16384
#define Mm (Tt*LB)        // 65536
#define N3 (3*Ee)         // 1536
#define FIX_CAP (1u<<20)
#define DELTA 2.5e-3f

// Scratch (device globals, allocation-free rule)
static __device__ __half   g_a0  [(size_t)Mm * Ee];   // query (fp16)
static __device__ __half   g_w0  [N3 * Ee];           // W_in (fp16)
static __device__ uint8_t  g_spk [(size_t)Mm * N3];   // qkv spikes (u8)
static __device__ __half   g_qh  [(size_t)Mm * Ee];   // q spikes (fp16 sidecar)
static __device__ __half   g_attn[Tt * 64 * 64 * 64]; // attn^T counts (exact fp16)
static __device__ __half   g_s2  [(size_t)Mm * Ee];   // s2 spikes (fp16 0/1)
static __device__ __half   g_whi [Ee * Ee];           // W_out (fp16)
static __device__ unsigned int g_nflag;
static __device__ unsigned int g_list[FIX_CAP];

__device__ __forceinline__ void ldsm_x4(uint32_t& r0, uint32_t& r1,
                                        uint32_t& r2, uint32_t& r3,
                                        const void* p)
{
    uint32_t a = (uint32_t)__cvta_generic_to_shared(p);
    asm volatile("ldmatrix.sync.aligned.m8n8.x4.shared.b16 {%0,%1,%2,%3}, [%4];"
                 : "=r"(r0), "=r"(r1), "=r"(r2), "=r"(r3) : "r"(a));
}

__device__ __forceinline__ void cp16(void* dst, const void* src)
{
    uint32_t d = (uint32_t)__cvta_generic_to_shared(dst);
    asm volatile("cp.async.cg.shared.global [%0], [%1], 16;" :: "r"(d), "l"(src));
}
#define CP_COMMIT() asm volatile("cp.async.commit_group;")
#define CP_WAIT1()  asm volatile("cp.async.wait_group 1;")
#define CP_WAIT0()  asm volatile("cp.async.wait_group 0;")

#define MMA_F16(acc, a0, a1, a2, a3, b0, b1)                                \
    asm volatile(                                                           \
        "mma.sync.aligned.m16n8k16.row.col.f32.f16.f16.f32 "                \
        "{%0,%1,%2,%3}, {%4,%5,%6,%7}, {%8,%9}, {%0,%1,%2,%3};"             \
        : "+f"(acc[0]), "+f"(acc[1]), "+f"(acc[2]), "+f"(acc[3])            \
        : "r"(a0), "r"(a1), "r"(a2), "r"(a3), "r"(b0), "r"(b1))

#define STG 5120     // gemm stage stride: 128 rows x 40 halves
#define VST 132      // epilogue fp32 tile stride
#define KVS 136      // kv transpose tile stride (16B-aligned rows)
#define H1(u) ((unsigned short)((u) * 0x3C00u))

// ---------------------------------------------------------------------------
// fp32 -> fp16 convert (query, W_in, W_out)
// ---------------------------------------------------------------------------
__global__ __launch_bounds__(256) void conv_kernel(
    const float* __restrict__ src, __half* __restrict__ d0)
{
    size_t i4 = ((size_t)blockIdx.x * 256 + threadIdx.x) * 4;
    float4 v = *(const float4*)(src + i4);
    __half h[4] = {__float2half_rn(v.x), __float2half_rn(v.y),
                   __float2half_rn(v.z), __float2half_rn(v.w)};
    *(uint2*)(d0 + i4) = *(uint2*)h;
}

__global__ void zero_flag_kernel() { g_nflag = 0u; }

// ---------------------------------------------------------------------------
// Fused GEMM1 + LIF (validated R14): t-interleaved tile rows, single fp16
// mma pass, smem-staged epilogue with LIF scan + flag + spike writes.
// Also writes q-part spikes as fp16 to g_qh (sidecar).
// ---------------------------------------------------------------------------
__global__ __launch_bounds__(256) void gemm1_lif_kernel(
    const float* __restrict__ bias)
{
    extern __shared__ __half dsm[];
    __half* A0s = dsm;              // [2][128][40] (pipeline phase)
    __half* B0s = dsm + 2*STG;
    float*  vsm = (float*)dsm;      // [128][VST]  (epilogue phase, reuse)

    const int bn   = blockIdx.x * 128;   // f tile
    const int bm32 = blockIdx.y * 32;    // lb tile (32 lbs x 4 t)
    const int tid  = threadIdx.x;
    const int wid  = tid >> 5;
    const int lane = tid & 31;
    const int wm = wid >> 1;
    const int wn = wid & 1;
    const int lr = lane >> 2;
    const int lc = (lane & 3) * 2;

    const int a_r = lane & 15, a_k = (lane >> 4) * 8;
    const int b_r = (lane & 7) + ((lane >> 4) << 3);
    const int b_k = ((lane >> 3) & 1) * 8;

    float bc[8][2];
    #pragma unroll
    for (int ni = 0; ni < 8; ni++) {
        int col = bn + wn*64 + ni*8 + lc;
        bc[ni][0] = bias[col];
        bc[ni][1] = bias[col + 1];
    }

    float acc[2][8][4];
    #pragma unroll
    for (int mi = 0; mi < 2; mi++)
        #pragma unroll
        for (int ni = 0; ni < 8; ni++)
            #pragma unroll
            for (int r = 0; r < 4; r++) acc[mi][ni][r] = 0.f;

    auto load_stage = [&](int s, int k0) {
        #pragma unroll
        for (int i = tid; i < 512; i += 256) {
            int row = i >> 2, c8 = (i & 3) << 3;
            int so = s*STG + row*40 + c8;
            int lb = bm32 + (row >> 2);
            int t  = row & 3;
            cp16(A0s + so, g_a0 + ((size_t)t * LB + lb) * Ee + k0 + c8);
            cp16(B0s + so, g_w0 + (size_t)(bn + row) * Ee + k0 + c8);
        }
    };

    load_stage(0, 0);
    CP_COMMIT();

    const int NT = Ee / 32;   // 16
    for (int it = 0; it < NT; it++) {
        if (it + 1 < NT) {
            load_stage((it + 1) & 1, (it + 1) * 32);
            CP_COMMIT();
            CP_WAIT1();
        } else {
            CP_WAIT0();
        }
        __syncthreads();

        const int sb = (it & 1) * STG;
        #pragma unroll
        for (int kk = 0; kk < 32; kk += 16) {
            uint32_t a0[2][4];
            #pragma unroll
            for (int mi = 0; mi < 2; mi++) {
                int rb = wm*32 + mi*16;
                ldsm_x4(a0[mi][0], a0[mi][1], a0[mi][2], a0[mi][3],
                        A0s + sb + (rb + a_r)*40 + kk + a_k);
            }
            uint32_t bh[8][2];
            #pragma unroll
            for (int nb = 0; nb < 4; nb++) {
                int n0 = wn*64 + nb*16;
                ldsm_x4(bh[nb*2][0], bh[nb*2][1], bh[nb*2+1][0], bh[nb*2+1][1],
                        B0s + sb + (n0 + b_r)*40 + kk + b_k);
            }
            #pragma unroll
            for (int ni = 0; ni < 8; ni++) {
                #pragma unroll
                for (int mi = 0; mi < 2; mi++) {
                    MMA_F16(acc[mi][ni], a0[mi][0], a0[mi][1], a0[mi][2],
                            a0[mi][3], bh[ni][0], bh[ni][1]);
                }
            }
        }
        __syncthreads();
    }

    // Phase 1: stage acc+bias into smem fp32 tile
    #pragma unroll
    for (int mi = 0; mi < 2; mi++) {
        #pragma unroll
        for (int ni = 0; ni < 8; ni++) {
            #pragma unroll
            for (int rp = 0; rp < 2; rp++) {
                int row = wm*32 + mi*16 + lr + rp*8;
                int col = wn*64 + ni*8 + lc;
                vsm[row*VST + col]     = acc[mi][ni][rp*2]     + bc[ni][0];
                vsm[row*VST + col + 1] = acc[mi][ni][rp*2 + 1] + bc[ni][1];
            }
        }
    }
    __syncthreads();

    // Phase 2: LIF scan per neuron; write u8 spikes (+fp16 sidecar for q)
    const bool isq = (bn < Ee);
    for (int j = tid; j < 4096; j += 256) {
        int f   = j & 127;
        int lbl = j >> 7;
        float v = 0.f;
        bool flag = false;
        #pragma unroll
        for (int t = 0; t < Tt; t++) {
            float x = vsm[(lbl*4 + t)*VST + f];
            float h = v + (x - v) * 0.5f;
            flag |= fabsf(h - 1.0f) < DELTA;
            bool s = (h - 1.0f) >= 0.f;
            g_spk[(size_t)t * LB * N3 + (size_t)(bm32 + lbl) * N3 + bn + f]
                = s ? 1 : 0;
            if (isq)
                g_qh[(size_t)t * LB * Ee + (size_t)(bm32 + lbl) * Ee + bn + f]
                    = __ushort_as_half(s ? 0x3C00 : 0);
            v = s ? 0.f : h;
        }
        if (flag) {
            unsigned int p = atomicAdd(&g_nflag, 1u);
            if (p < FIX_CAP)
                g_list[p] = (unsigned int)((size_t)(bm32 + lbl) * N3 + bn + f);
        }
    }
}

// ---------------------------------------------------------------------------
// Exact fixup, block-cooperative: 32 neurons/block. W + Q rows staged in smem
// (coalesced float4 global loads, SCALAR smem stores -> no alignment issue,
// stride 33 conflict-free). 128 threads each run one (neuron, t) sequential
// ascending-k fp32 FMA chain — identical summation order, bit-exact.
// ---------------------------------------------------------------------------
__global__ __launch_bounds__(256) void fixup_kernel(
    const float* __restrict__ Q, const float* __restrict__ W,
    const float* __restrict__ bias)
{
    __shared__ float wch[32][33];    // [neuron][k within chunk]
    __shared__ float qch[128][33];   // [neuron*4+t][k within chunk]
    __shared__ float accs[128];
    __shared__ int   s_lb[32];
    __shared__ int   s_f [32];

    unsigned int n = g_nflag; if (n > FIX_CAP) n = FIX_CAP;
    unsigned int base = blockIdx.x * 32;
    if (base >= n) return;
    const int tid = threadIdx.x;

    if (tid < 32) {
        unsigned int g = base + (unsigned)tid;
        unsigned int i = (g < n) ? g_list[g] : g_list[base];
        s_lb[tid] = (int)(i / N3);
        s_f [tid] = (int)(i - (i / N3) * N3);
    }
    __syncthreads();

    const int j   = tid >> 3;        // load: neuron 0..31
    const int sub = tid & 7;         // load: float4 within 32-k chunk
    const int cj = tid >> 2;         // compute: neuron
    const int ct = tid & 3;          // compute: t

    float acc = 0.f;
    for (int c = 0; c < 16; c++) {
        int k0 = c * 32;
        __syncthreads();
        float4 wv = *(const float4*)(W + (size_t)s_f[j] * Ee + k0 + sub*4);
        wch[j][sub*4+0] = wv.x; wch[j][sub*4+1] = wv.y;
        wch[j][sub*4+2] = wv.z; wch[j][sub*4+3] = wv.w;
        #pragma unroll
        for (int tq = 0; tq < Tt; tq++) {
            float4 qv = *(const float4*)(
                Q + ((size_t)tq * LB + s_lb[j]) * Ee + k0 + sub*4);
            qch[j*4 + tq][sub*4+0] = qv.x; qch[j*4 + tq][sub*4+1] = qv.y;
            qch[j*4 + tq][sub*4+2] = qv.z; qch[j*4 + tq][sub*4+3] = qv.w;
        }
        __syncthreads();

        if (tid < 128) {
            #pragma unroll
            for (int k = 0; k < 32; k++)
                acc = fmaf(qch[cj*4 + ct][k], wch[cj][k], acc);
        }
    }

    if (tid < 128) accs[tid] = acc;
    __syncthreads();

    if (tid < 32) {
        unsigned int g = base + (unsigned)tid;
        if (g < n) {
            int lb = s_lb[tid], f = s_f[tid];
            float b = bias[f];
            float v = 0.f;
            #pragma unroll
            for (int t = 0; t < Tt; t++) {
                float x = accs[tid*4 + t] + b;
                float h = v + (x - v) * 0.5f;
                bool s = (h - 1.0f) >= 0.f;
                g_spk[(size_t)t * LB * N3 + (size_t)lb * N3 + f] = s ? 1 : 0;
                if (f < Ee)
                    g_qh[(size_t)t * LB * Ee + (size_t)lb * Ee + f]
                        = __ushort_as_half(s ? 0x3C00 : 0);
                v = s ? 0.f : h;
            }
        }
    }
}

// ---------------------------------------------------------------------------
// kv attention on tensor cores (validated R9): attnT[e][d] = sum_l v*k.
// ---------------------------------------------------------------------------
__global__ __launch_bounds__(256) void kv_attn_kernel()
{
    const int n = blockIdx.x, t = blockIdx.y;
    const int b = n >> 3, h = n & 7;
    __shared__ __half vT[64 * KVS];
    __shared__ __half kT[64 * KVS];

    const int tid  = threadIdx.x;
    const int wid  = tid >> 5;
    const int lane = tid & 31;
    const int e0 = (wid >> 1) * 16;
    const int d0 = (wid & 1) * 32;
    const int lr = lane >> 2;
    const int lc = (lane & 3) * 2;

    const int a_r = lane & 15, a_k = (lane >> 4) * 8;
    const int b_r = (lane & 7) + ((lane >> 4) << 3);
    const int b_k = ((lane >> 3) & 1) * 8;

    float acc[4][4];
    #pragma unroll
    for (int ni = 0; ni < 4; ni++)
        #pragma unroll
        for (int r = 0; r < 4; r++) acc[ni][r] = 0.f;

    for (int l0 = 0; l0 < Ll; l0 += 128) {
        __syncthreads();
        for (int i = tid; i < 2048; i += 256) {
            int ll = i >> 4, d4 = (i & 15) << 2;
            size_t base = ((size_t)t * LB + (size_t)(l0 + ll) * Bb + b) * N3
                          + h * 64 + d4;
            uchar4 kc = *(const uchar4*)(g_spk + base + 512);
            uchar4 vc = *(const uchar4*)(g_spk + base + 1024);
            kT[(d4+0)*KVS + ll] = __ushort_as_half(H1(kc.x));
            kT[(d4+1)*KVS + ll] = __ushort_as_half(H1(kc.y));
            kT[(d4+2)*KVS + ll] = __ushort_as_half(H1(kc.z));
            kT[(d4+3)*KVS + ll] = __ushort_as_half(H1(kc.w));
            vT[(d4+0)*KVS + ll] = __ushort_as_half(H1(vc.x));
            vT[(d4+1)*KVS + ll] = __ushort_as_half(H1(vc.y));
            vT[(d4+2)*KVS + ll] = __ushort_as_half(H1(vc.z));
            vT[(d4+3)*KVS + ll] = __ushort_as_half(H1(vc.w));
        }
        __syncthreads();

        #pragma unroll
        for (int kk = 0; kk < 128; kk += 16) {
            uint32_t a[4];
            ldsm_x4(a[0], a[1], a[2], a[3], &vT[(e0 + a_r)*KVS + kk + a_k]);
            uint32_t bt[4][2];
            #pragma unroll
            for (int nb = 0; nb < 2; nb++)
                ldsm_x4(bt[nb*2][0], bt[nb*2][1], bt[nb*2+1][0], bt[nb*2+1][1],
                        &kT[(d0 + nb*16 + b_r)*KVS + kk + b_k]);
            #pragma unroll
            for (int ni = 0; ni < 4; ni++)
                MMA_F16(acc[ni], a[0], a[1], a[2], a[3], bt[ni][0], bt[ni][1]);
        }
    }

    __half* ap = g_attn + (size_t)(t * 64 + n) * 4096;
    #pragma unroll
    for (int ni = 0; ni < 4; ni++) {
        int d = d0 + ni*8 + lc;
        *(__half2*)(ap + (e0 + lr) * 64 + d) =
            __floats2half2_rn(acc[ni][0], acc[ni][1]);
        *(__half2*)(ap + (e0 + lr + 8) * 64 + d) =
            __floats2half2_rn(acc[ni][2], acc[ni][3]);
    }
}

// ---------------------------------------------------------------------------
// q @ attn on tensor cores + fused LIF(0.5) (validated R9). q-spike fill
// reads the fp16 sidecar (plain uint4 copies).
// ---------------------------------------------------------------------------
__global__ __launch_bounds__(256) void qattn_lif_kernel()
{
    const int n = blockIdx.y, lt = blockIdx.x;
    const int b = n >> 3, h = n & 7;
    __shared__ __half qs[128][72];
    __shared__ __half at[64][72];

    const int tid  = threadIdx.x;
    const int wid  = tid >> 5;
    const int lane = tid & 31;
    const int wm = wid >> 1;
    const int wn = wid & 1;
    const int lr = lane >> 2;
    const int lc = (lane & 3) * 2;

    const int a_r = lane & 15, a_k = (lane >> 4) * 8;
    const int b_r = (lane & 7) + ((lane >> 4) << 3);
    const int b_k = ((lane >> 3) & 1) * 8;

    float vmem[2][4][4];
    #pragma unroll
    for (int mi = 0; mi < 2; mi++)
        #pragma unroll
        for (int ni = 0; ni < 4; ni++)
            #pragma unroll
            for (int r = 0; r < 4; r++) vmem[mi][ni][r] = 0.f;

    for (int t = 0; t < Tt; t++) {
        __syncthreads();
        for (int i = tid; i < 1024; i += 256) {
            int ll = i >> 3, c8 = (i & 7) << 3;
            size_t base = ((size_t)t * LB + (size_t)(lt*128 + ll) * Bb + b) * Ee
                          + h * 64 + c8;
            *(uint4*)&qs[ll][c8] = *(const uint4*)(g_qh + base);
        }
        for (int i = tid; i < 512; i += 256) {
            int row = i >> 3, c8 = (i & 7) << 3;
            *(uint4*)&at[row][c8] =
                *(const uint4*)(g_attn + (size_t)(t*64 + n) * 4096 + row*64 + c8);
        }
        __syncthreads();

        float acc[2][4][4];
        #pragma unroll
        for (int mi = 0; mi < 2; mi++)
            #pragma unroll
            for (int ni = 0; ni < 4; ni++)
                #pragma unroll
                for (int r = 0; r < 4; r++) acc[mi][ni][r] = 0.f;

        #pragma unroll
        for (int kk = 0; kk < 64; kk += 16) {
            uint32_t a[2][4];
            #pragma unroll
            for (int mi = 0; mi < 2; mi++)
                ldsm_x4(a[mi][0], a[mi][1], a[mi][2], a[mi][3],
                        &qs[wm*32 + mi*16 + a_r][kk + a_k]);
            uint32_t bt[4][2];
            #pragma unroll
            for (int nb = 0; nb < 2; nb++)
                ldsm_x4(bt[nb*2][0], bt[nb*2][1], bt[nb*2+1][0], bt[nb*2+1][1],
                        &at[wn*32 + nb*16 + b_r][kk + b_k]);
            #pragma unroll
            for (int ni = 0; ni < 4; ni++)
                #pragma unroll
                for (int mi = 0; mi < 2; mi++)
                    MMA_F16(acc[mi][ni], a[mi][0], a[mi][1], a[mi][2], a[mi][3],
                            bt[ni][0], bt[ni][1]);
        }

        #pragma unroll
        for (int mi = 0; mi < 2; mi++) {
            #pragma unroll
            for (int ni = 0; ni < 4; ni++) {
                int e = wn*32 + ni*8 + lc;
                #pragma unroll
                for (int rp = 0; rp < 2; rp++) {
                    int l = lt*128 + wm*32 + mi*16 + lr + rp*8;
                    unsigned short sp[2];
                    #pragma unroll
                    for (int c = 0; c < 2; c++) {
                        int r = rp*2 + c;
                        float x = acc[mi][ni][r] * 0.125f;
                        float v = vmem[mi][ni][r];
                        float hh = v + (x - v) * 0.5f;
                        bool s = (hh - 0.5f) >= 0.f;
                        sp[c] = s ? 0x3C00 : 0;
                        vmem[mi][ni][r] = s ? 0.f : hh;
                    }
                    *(uint32_t*)(g_s2 + (((size_t)t * Ll + l) * Bb + b) * Ee
                                 + h * 64 + e) = *(uint32_t*)sp;
                }
            }
        }
    }
}

// ---------------------------------------------------------------------------
// GEMM5: out = s2 @ W_out^T + bias, single fp16 pass (validated R13).
// ---------------------------------------------------------------------------
__global__ __launch_bounds__(256) void gemm5_mma_kernel(
    const float* __restrict__ bias, float* __restrict__ C)
{
    extern __shared__ __half dsm[];
    __half* As  = dsm;              // [2][128][40]
    __half* Bhi = dsm + 2*STG;

    const int bm = blockIdx.y * 128;
    const int bn = blockIdx.x * 128;
    const int tid  = threadIdx.x;
    const int wid  = tid >> 5;
    const int lane = tid & 31;
    const int wm = wid >> 1;
    const int wn = wid & 1;
    const int lr = lane >> 2;
    const int lc = (lane & 3) * 2;

    const int a_r = lane & 15, a_k = (lane >> 4) * 8;
    const int b_r = (lane & 7) + ((lane >> 4) << 3);
    const int b_k = ((lane >> 3) & 1) * 8;

    float acc[2][8][4];
    #pragma unroll
    for (int mi = 0; mi < 2; mi++)
        #pragma unroll
        for (int ni = 0; ni < 8; ni++)
            #pragma unroll
            for (int r = 0; r < 4; r++) acc[mi][ni][r] = 0.f;

    auto load_stage = [&](int s, int k0) {
        #pragma unroll
        for (int i = tid; i < 512; i += 256) {
            int row = i >> 2, c8 = (i & 3) << 3;
            int so = s*STG + row*40 + c8;
            cp16(As + so, g_s2 + (size_t)(bm + row) * Ee + k0 + c8);
            cp16(Bhi + so, g_whi + (size_t)(bn + row) * Ee + k0 + c8);
        }
    };

    load_stage(0, 0);
    CP_COMMIT();

    const int NT = Ee / 32;
    for (int it = 0; it < NT; it++) {
        if (it + 1 < NT) {
            load_stage((it + 1) & 1, (it + 1) * 32);
            CP_COMMIT();
            CP_WAIT1();
        } else {
            CP_WAIT0();
        }
        __syncthreads();

        const int sb = (it & 1) * STG;
        #pragma unroll
        for (int kk = 0; kk < 32; kk += 16) {
            uint32_t a[2][4];
            #pragma unroll
            for (int mi = 0; mi < 2; mi++) {
                int rb = wm*32 + mi*16;
                ldsm_x4(a[mi][0], a[mi][1], a[mi][2], a[mi][3],
                        As + sb + (rb + a_r)*40 + kk + a_k);
            }
            uint32_t bh[8][2];
            #pragma unroll
            for (int nb = 0; nb < 4; nb++) {
                int n0 = wn*64 + nb*16;
                ldsm_x4(bh[nb*2][0], bh[nb*2][1], bh[nb*2+1][0], bh[nb*2+1][1],
                        Bhi + sb + (n0 + b_r)*40 + kk + b_k);
            }
            #pragma unroll
            for (int ni = 0; ni < 8; ni++) {
                #pragma unroll
                for (int mi = 0; mi < 2; mi++) {
                    MMA_F16(acc[mi][ni], a[mi][0], a[mi][1], a[mi][2], a[mi][3],
                            bh[ni][0], bh[ni][1]);
                }
            }
        }
        __syncthreads();
    }

    #pragma unroll
    for (int mi = 0; mi < 2; mi++) {
        #pragma unroll
        for (int ni = 0; ni < 8; ni++) {
            int col = bn + wn*64 + ni*8 + lc;
            float b0 = bias[col], b1 = bias[col + 1];
            int row0 = bm + wm*32 + mi*16 + lr;
            *(float2*)(C + (size_t)row0 * Ee + col) =
                make_float2(acc[mi][ni][0] + b0, acc[mi][ni][1] + b1);
            *(float2*)(C + (size_t)(row0 + 8) * Ee + col) =
                make_float2(acc[mi][ni][2] + b0, acc[mi][ni][3] + b1);
        }
    }
}

// ---------------------------------------------------------------------------
extern "C" void kernel_launch(void* const* d_in, const int* in_sizes, int n_in,
                              void* d_out, int out_size)
{
    const float* query = (const float*)d_in[0];   // (T,L,B,E)
    const float* w_in  = (const float*)d_in[1];   // (3E, E)
    const float* b_in  = (const float*)d_in[2];   // (3E)
    const float* w_out = (const float*)d_in[3];   // (E, E)
    const float* b_out = (const float*)d_in[4];   // (E)
    float* out = (float*)d_out;                   // (T,L,B,E)

    void *p_a0, *p_w0, *p_whi;
    cudaGetSymbolAddress(&p_a0, g_a0);
    cudaGetSymbolAddress(&p_w0, g_w0);
    cudaGetSymbolAddress(&p_whi, g_whi);

    // 0) zero flag counter + fp16 converts
    zero_flag_kernel<<<1, 1>>>();
    conv_kernel<<<((size_t)Mm * Ee / 4) / 256, 256>>>(query, (__half*)p_a0);
    conv_kernel<<<((size_t)N3 * Ee / 4) / 256, 256>>>(w_in, (__half*)p_w0);
    conv_kernel<<<((size_t)Ee * Ee / 4) / 256, 256>>>(w_out, (__half*)p_whi);

    // 1) fused proj + LIF + flag on tensor cores (t-interleaved tiles)
    const int SM1 = 128 * VST * 4;   // 66 KB
    cudaFuncSetAttribute(gemm1_lif_kernel,
                         cudaFuncAttributeMaxDynamicSharedMemorySize, SM1);
    gemm1_lif_kernel<<<dim3(N3 / 128, LB / 32), 256, SM1>>>(b_in);

    // 2) exact fixup of flagged neurons (block-cooperative, bit-exact order)
    fixup_kernel<<<FIX_CAP / 32, 256>>>(query, w_in, b_in);

    // 3) attnT = v^T k per (t, head) on tensor cores
    kv_attn_kernel<<<dim3(64, Tt), 256>>>();

    // 4) out = q @ attn * 0.125 -> LIF(0.5) -> s2 spikes, tensor cores
    qattn_lif_kernel<<<dim3(Ll / 128, 64), 256>>>();

    // 5) final = s2 @ W_out^T + b_out, single fp16 pass
    const int SM5 = 4 * STG * (int)sizeof(__half);   // 40 KB
    cudaFuncSetAttribute(gemm5_mma_kernel,
                         cudaFuncAttributeMaxDynamicSharedMemorySize, SM5);
    gemm5_mma_kernel<<<dim3(Ee / 128, Mm / 128), 256, SM5>>>(b_out, out);
}

// round 17
// speedup vs baseline: 2.2108x; 1.0998x over previous
#include <cuda_runtime.h>
#include <cuda_fp16.h>
#include <cstdint>

// Problem dims (fixed)
#define Tt 4
#define Ll 2048
#define Bb 8
#define Ee 512
#define LB (Ll*Bb)        // 16384
#define Mm (Tt*LB)        // 65536
#define N3 (3*Ee)         // 1536
#define FIX_CAP (1u<<20)
#define DELTA 2.5e-3f

// Scratch (device globals, allocation-free rule)
static __device__ __half   g_a0  [(size_t)Mm * Ee];   // query (fp16)
static __device__ __half   g_w0  [N3 * Ee];           // W_in (fp16)
static __device__ uint8_t  g_spk [(size_t)Mm * N3];   // qkv spikes (u8)
static __device__ __half   g_qh  [(size_t)Mm * Ee];   // q spikes (fp16 sidecar)
static __device__ __half   g_attn[Tt * 64 * 64 * 64]; // attn^T counts (exact fp16)
static __device__ __half   g_s2  [(size_t)Mm * Ee];   // s2 spikes (fp16 0/1)
static __device__ __half   g_whi [Ee * Ee];           // W_out (fp16)
static __device__ unsigned int g_nflag;
static __device__ unsigned int g_list[FIX_CAP];

__device__ __forceinline__ void ldsm_x4(uint32_t& r0, uint32_t& r1,
                                        uint32_t& r2, uint32_t& r3,
                                        const void* p)
{
    uint32_t a = (uint32_t)__cvta_generic_to_shared(p);
    asm volatile("ldmatrix.sync.aligned.m8n8.x4.shared.b16 {%0,%1,%2,%3}, [%4];"
                 : "=r"(r0), "=r"(r1), "=r"(r2), "=r"(r3) : "r"(a));
}

__device__ __forceinline__ void cp16(void* dst, const void* src)
{
    uint32_t d = (uint32_t)__cvta_generic_to_shared(dst);
    asm volatile("cp.async.cg.shared.global [%0], [%1], 16;" :: "r"(d), "l"(src));
}
#define CP_COMMIT() asm volatile("cp.async.commit_group;")
#define CP_WAIT1()  asm volatile("cp.async.wait_group 1;")
#define CP_WAIT0()  asm volatile("cp.async.wait_group 0;")

#define MMA_F16(acc, a0, a1, a2, a3, b0, b1)                                \
    asm volatile(                                                           \
        "mma.sync.aligned.m16n8k16.row.col.f32.f16.f16.f32 "                \
        "{%0,%1,%2,%3}, {%4,%5,%6,%7}, {%8,%9}, {%0,%1,%2,%3};"             \
        : "+f"(acc[0]), "+f"(acc[1]), "+f"(acc[2]), "+f"(acc[3])            \
        : "r"(a0), "r"(a1), "r"(a2), "r"(a3), "r"(b0), "r"(b1))

#define STG64 9216   // BK=64 stage stride: 128 rows x 72 halves
#define VST 132      // epilogue fp32 tile stride
#define KVS 136      // kv transpose tile stride (16B-aligned rows)
#define H1(u) ((unsigned short)((u) * 0x3C00u))

// ---------------------------------------------------------------------------
// fp32 -> fp16 convert (query, W_in, W_out)
// ---------------------------------------------------------------------------
__global__ __launch_bounds__(256) void conv_kernel(
    const float* __restrict__ src, __half* __restrict__ d0)
{
    size_t i4 = ((size_t)blockIdx.x * 256 + threadIdx.x) * 4;
    float4 v = *(const float4*)(src + i4);
    __half h[4] = {__float2half_rn(v.x), __float2half_rn(v.y),
                   __float2half_rn(v.z), __float2half_rn(v.w)};
    *(uint2*)(d0 + i4) = *(uint2*)h;
}

__global__ void zero_flag_kernel() { g_nflag = 0u; }

// ---------------------------------------------------------------------------
// Fused GEMM1 + LIF (validated R14/R16): t-interleaved tile rows, single
// fp16 mma pass, BK=64 cp.async stages (8 syncs instead of 16), smem-staged
// epilogue with LIF scan + flag + spike writes (+fp16 q sidecar).
// k-accumulation order identical to R16 -> bit-identical results.
// ---------------------------------------------------------------------------
__global__ __launch_bounds__(256) void gemm1_lif_kernel(
    const float* __restrict__ bias)
{
    extern __shared__ __half dsm[];
    __half* A0s = dsm;              // [2][128][72] (pipeline phase)
    __half* B0s = dsm + 2*STG64;
    float*  vsm = (float*)dsm;      // [128][VST]  (epilogue phase, reuse)

    const int bn   = blockIdx.x * 128;   // f tile
    const int bm32 = blockIdx.y * 32;    // lb tile (32 lbs x 4 t)
    const int tid  = threadIdx.x;
    const int wid  = tid >> 5;
    const int lane = tid & 31;
    const int wm = wid >> 1;
    const int wn = wid & 1;
    const int lr = lane >> 2;
    const int lc = (lane & 3) * 2;

    const int a_r = lane & 15, a_k = (lane >> 4) * 8;
    const int b_r = (lane & 7) + ((lane >> 4) << 3);
    const int b_k = ((lane >> 3) & 1) * 8;

    float bc[8][2];
    #pragma unroll
    for (int ni = 0; ni < 8; ni++) {
        int col = bn + wn*64 + ni*8 + lc;
        bc[ni][0] = bias[col];
        bc[ni][1] = bias[col + 1];
    }

    float acc[2][8][4];
    #pragma unroll
    for (int mi = 0; mi < 2; mi++)
        #pragma unroll
        for (int ni = 0; ni < 8; ni++)
            #pragma unroll
            for (int r = 0; r < 4; r++) acc[mi][ni][r] = 0.f;

    auto load_stage = [&](int s, int k0) {
        #pragma unroll
        for (int i = tid; i < 1024; i += 256) {
            int row = i >> 3, c8 = (i & 7) << 3;
            int so = s*STG64 + row*72 + c8;
            int lb = bm32 + (row >> 2);
            int t  = row & 3;
            cp16(A0s + so, g_a0 + ((size_t)t * LB + lb) * Ee + k0 + c8);
            cp16(B0s + so, g_w0 + (size_t)(bn + row) * Ee + k0 + c8);
        }
    };

    load_stage(0, 0);
    CP_COMMIT();

    const int NT = Ee / 64;   // 8
    for (int it = 0; it < NT; it++) {
        if (it + 1 < NT) {
            load_stage((it + 1) & 1, (it + 1) * 64);
            CP_COMMIT();
            CP_WAIT1();
        } else {
            CP_WAIT0();
        }
        __syncthreads();

        const int sb = (it & 1) * STG64;
        #pragma unroll
        for (int kk = 0; kk < 64; kk += 16) {
            uint32_t a0[2][4];
            #pragma unroll
            for (int mi = 0; mi < 2; mi++) {
                int rb = wm*32 + mi*16;
                ldsm_x4(a0[mi][0], a0[mi][1], a0[mi][2], a0[mi][3],
                        A0s + sb + (rb + a_r)*72 + kk + a_k);
            }
            uint32_t bh[8][2];
            #pragma unroll
            for (int nb = 0; nb < 4; nb++) {
                int n0 = wn*64 + nb*16;
                ldsm_x4(bh[nb*2][0], bh[nb*2][1], bh[nb*2+1][0], bh[nb*2+1][1],
                        B0s + sb + (n0 + b_r)*72 + kk + b_k);
            }
            #pragma unroll
            for (int ni = 0; ni < 8; ni++) {
                #pragma unroll
                for (int mi = 0; mi < 2; mi++) {
                    MMA_F16(acc[mi][ni], a0[mi][0], a0[mi][1], a0[mi][2],
                            a0[mi][3], bh[ni][0], bh[ni][1]);
                }
            }
        }
        __syncthreads();
    }

    // Phase 1: stage acc+bias into smem fp32 tile
    #pragma unroll
    for (int mi = 0; mi < 2; mi++) {
        #pragma unroll
        for (int ni = 0; ni < 8; ni++) {
            #pragma unroll
            for (int rp = 0; rp < 2; rp++) {
                int row = wm*32 + mi*16 + lr + rp*8;
                int col = wn*64 + ni*8 + lc;
                vsm[row*VST + col]     = acc[mi][ni][rp*2]     + bc[ni][0];
                vsm[row*VST + col + 1] = acc[mi][ni][rp*2 + 1] + bc[ni][1];
            }
        }
    }
    __syncthreads();

    // Phase 2: LIF scan per neuron; write u8 spikes (+fp16 sidecar for q)
    const bool isq = (bn < Ee);
    for (int j = tid; j < 4096; j += 256) {
        int f   = j & 127;
        int lbl = j >> 7;
        float v = 0.f;
        bool flag = false;
        #pragma unroll
        for (int t = 0; t < Tt; t++) {
            float x = vsm[(lbl*4 + t)*VST + f];
            float h = v + (x - v) * 0.5f;
            flag |= fabsf(h - 1.0f) < DELTA;
            bool s = (h - 1.0f) >= 0.f;
            g_spk[(size_t)t * LB * N3 + (size_t)(bm32 + lbl) * N3 + bn + f]
                = s ? 1 : 0;
            if (isq)
                g_qh[(size_t)t * LB * Ee + (size_t)(bm32 + lbl) * Ee + bn + f]
                    = __ushort_as_half(s ? 0x3C00 : 0);
            v = s ? 0.f : h;
        }
        if (flag) {
            unsigned int p = atomicAdd(&g_nflag, 1u);
            if (p < FIX_CAP)
                g_list[p] = (unsigned int)((size_t)(bm32 + lbl) * N3 + bn + f);
        }
    }
}

// ---------------------------------------------------------------------------
// Exact fixup (validated R16): block-cooperative, bit-exact order.
// ---------------------------------------------------------------------------
__global__ __launch_bounds__(256) void fixup_kernel(
    const float* __restrict__ Q, const float* __restrict__ W,
    const float* __restrict__ bias)
{
    __shared__ float wch[32][33];
    __shared__ float qch[128][33];
    __shared__ float accs[128];
    __shared__ int   s_lb[32];
    __shared__ int   s_f [32];

    unsigned int n = g_nflag; if (n > FIX_CAP) n = FIX_CAP;
    unsigned int base = blockIdx.x * 32;
    if (base >= n) return;
    const int tid = threadIdx.x;

    if (tid < 32) {
        unsigned int g = base + (unsigned)tid;
        unsigned int i = (g < n) ? g_list[g] : g_list[base];
        s_lb[tid] = (int)(i / N3);
        s_f [tid] = (int)(i - (i / N3) * N3);
    }
    __syncthreads();

    const int j   = tid >> 3;
    const int sub = tid & 7;
    const int cj = tid >> 2;
    const int ct = tid & 3;

    float acc = 0.f;
    for (int c = 0; c < 16; c++) {
        int k0 = c * 32;
        __syncthreads();
        float4 wv = *(const float4*)(W + (size_t)s_f[j] * Ee + k0 + sub*4);
        wch[j][sub*4+0] = wv.x; wch[j][sub*4+1] = wv.y;
        wch[j][sub*4+2] = wv.z; wch[j][sub*4+3] = wv.w;
        #pragma unroll
        for (int tq = 0; tq < Tt; tq++) {
            float4 qv = *(const float4*)(
                Q + ((size_t)tq * LB + s_lb[j]) * Ee + k0 + sub*4);
            qch[j*4 + tq][sub*4+0] = qv.x; qch[j*4 + tq][sub*4+1] = qv.y;
            qch[j*4 + tq][sub*4+2] = qv.z; qch[j*4 + tq][sub*4+3] = qv.w;
        }
        __syncthreads();

        if (tid < 128) {
            #pragma unroll
            for (int k = 0; k < 32; k++)
                acc = fmaf(qch[cj*4 + ct][k], wch[cj][k], acc);
        }
    }

    if (tid < 128) accs[tid] = acc;
    __syncthreads();

    if (tid < 32) {
        unsigned int g = base + (unsigned)tid;
        if (g < n) {
            int lb = s_lb[tid], f = s_f[tid];
            float b = bias[f];
            float v = 0.f;
            #pragma unroll
            for (int t = 0; t < Tt; t++) {
                float x = accs[tid*4 + t] + b;
                float h = v + (x - v) * 0.5f;
                bool s = (h - 1.0f) >= 0.f;
                g_spk[(size_t)t * LB * N3 + (size_t)lb * N3 + f] = s ? 1 : 0;
                if (f < Ee)
                    g_qh[(size_t)t * LB * Ee + (size_t)lb * Ee + f]
                        = __ushort_as_half(s ? 0x3C00 : 0);
                v = s ? 0.f : h;
            }
        }
    }
}

// ---------------------------------------------------------------------------
// kv attention on tensor cores (validated R9): attnT[e][d] = sum_l v*k.
// ---------------------------------------------------------------------------
__global__ __launch_bounds__(256) void kv_attn_kernel()
{
    const int n = blockIdx.x, t = blockIdx.y;
    const int b = n >> 3, h = n & 7;
    __shared__ __half vT[64 * KVS];
    __shared__ __half kT[64 * KVS];

    const int tid  = threadIdx.x;
    const int wid  = tid >> 5;
    const int lane = tid & 31;
    const int e0 = (wid >> 1) * 16;
    const int d0 = (wid & 1) * 32;
    const int lr = lane >> 2;
    const int lc = (lane & 3) * 2;

    const int a_r = lane & 15, a_k = (lane >> 4) * 8;
    const int b_r = (lane & 7) + ((lane >> 4) << 3);
    const int b_k = ((lane >> 3) & 1) * 8;

    float acc[4][4];
    #pragma unroll
    for (int ni = 0; ni < 4; ni++)
        #pragma unroll
        for (int r = 0; r < 4; r++) acc[ni][r] = 0.f;

    for (int l0 = 0; l0 < Ll; l0 += 128) {
        __syncthreads();
        for (int i = tid; i < 2048; i += 256) {
            int ll = i >> 4, d4 = (i & 15) << 2;
            size_t base = ((size_t)t * LB + (size_t)(l0 + ll) * Bb + b) * N3
                          + h * 64 + d4;
            uchar4 kc = *(const uchar4*)(g_spk + base + 512);
            uchar4 vc = *(const uchar4*)(g_spk + base + 1024);
            kT[(d4+0)*KVS + ll] = __ushort_as_half(H1(kc.x));
            kT[(d4+1)*KVS + ll] = __ushort_as_half(H1(kc.y));
            kT[(d4+2)*KVS + ll] = __ushort_as_half(H1(kc.z));
            kT[(d4+3)*KVS + ll] = __ushort_as_half(H1(kc.w));
            vT[(d4+0)*KVS + ll] = __ushort_as_half(H1(vc.x));
            vT[(d4+1)*KVS + ll] = __ushort_as_half(H1(vc.y));
            vT[(d4+2)*KVS + ll] = __ushort_as_half(H1(vc.z));
            vT[(d4+3)*KVS + ll] = __ushort_as_half(H1(vc.w));
        }
        __syncthreads();

        #pragma unroll
        for (int kk = 0; kk < 128; kk += 16) {
            uint32_t a[4];
            ldsm_x4(a[0], a[1], a[2], a[3], &vT[(e0 + a_r)*KVS + kk + a_k]);
            uint32_t bt[4][2];
            #pragma unroll
            for (int nb = 0; nb < 2; nb++)
                ldsm_x4(bt[nb*2][0], bt[nb*2][1], bt[nb*2+1][0], bt[nb*2+1][1],
                        &kT[(d0 + nb*16 + b_r)*KVS + kk + b_k]);
            #pragma unroll
            for (int ni = 0; ni < 4; ni++)
                MMA_F16(acc[ni], a[0], a[1], a[2], a[3], bt[ni][0], bt[ni][1]);
        }
    }

    __half* ap = g_attn + (size_t)(t * 64 + n) * 4096;
    #pragma unroll
    for (int ni = 0; ni < 4; ni++) {
        int d = d0 + ni*8 + lc;
        *(__half2*)(ap + (e0 + lr) * 64 + d) =
            __floats2half2_rn(acc[ni][0], acc[ni][1]);
        *(__half2*)(ap + (e0 + lr + 8) * 64 + d) =
            __floats2half2_rn(acc[ni][2], acc[ni][3]);
    }
}

// ---------------------------------------------------------------------------
// q @ attn on tensor cores + fused LIF(0.5) (validated R9/R16).
// ---------------------------------------------------------------------------
__global__ __launch_bounds__(256) void qattn_lif_kernel()
{
    const int n = blockIdx.y, lt = blockIdx.x;
    const int b = n >> 3, h = n & 7;
    __shared__ __half qs[128][72];
    __shared__ __half at[64][72];

    const int tid  = threadIdx.x;
    const int wid  = tid >> 5;
    const int lane = tid & 31;
    const int wm = wid >> 1;
    const int wn = wid & 1;
    const int lr = lane >> 2;
    const int lc = (lane & 3) * 2;

    const int a_r = lane & 15, a_k = (lane >> 4) * 8;
    const int b_r = (lane & 7) + ((lane >> 4) << 3);
    const int b_k = ((lane >> 3) & 1) * 8;

    float vmem[2][4][4];
    #pragma unroll
    for (int mi = 0; mi < 2; mi++)
        #pragma unroll
        for (int ni = 0; ni < 4; ni++)
            #pragma unroll
            for (int r = 0; r < 4; r++) vmem[mi][ni][r] = 0.f;

    for (int t = 0; t < Tt; t++) {
        __syncthreads();
        for (int i = tid; i < 1024; i += 256) {
            int ll = i >> 3, c8 = (i & 7) << 3;
            size_t base = ((size_t)t * LB + (size_t)(lt*128 + ll) * Bb + b) * Ee
                          + h * 64 + c8;
            *(uint4*)&qs[ll][c8] = *(const uint4*)(g_qh + base);
        }
        for (int i = tid; i < 512; i += 256) {
            int row = i >> 3, c8 = (i & 7) << 3;
            *(uint4*)&at[row][c8] =
                *(const uint4*)(g_attn + (size_t)(t*64 + n) * 4096 + row*64 + c8);
        }
        __syncthreads();

        float acc[2][4][4];
        #pragma unroll
        for (int mi = 0; mi < 2; mi++)
            #pragma unroll
            for (int ni = 0; ni < 4; ni++)
                #pragma unroll
                for (int r = 0; r < 4; r++) acc[mi][ni][r] = 0.f;

        #pragma unroll
        for (int kk = 0; kk < 64; kk += 16) {
            uint32_t a[2][4];
            #pragma unroll
            for (int mi = 0; mi < 2; mi++)
                ldsm_x4(a[mi][0], a[mi][1], a[mi][2], a[mi][3],
                        &qs[wm*32 + mi*16 + a_r][kk + a_k]);
            uint32_t bt[4][2];
            #pragma unroll
            for (int nb = 0; nb < 2; nb++)
                ldsm_x4(bt[nb*2][0], bt[nb*2][1], bt[nb*2+1][0], bt[nb*2+1][1],
                        &at[wn*32 + nb*16 + b_r][kk + b_k]);
            #pragma unroll
            for (int ni = 0; ni < 4; ni++)
                #pragma unroll
                for (int mi = 0; mi < 2; mi++)
                    MMA_F16(acc[mi][ni], a[mi][0], a[mi][1], a[mi][2], a[mi][3],
                            bt[ni][0], bt[ni][1]);
        }

        #pragma unroll
        for (int mi = 0; mi < 2; mi++) {
            #pragma unroll
            for (int ni = 0; ni < 4; ni++) {
                int e = wn*32 + ni*8 + lc;
                #pragma unroll
                for (int rp = 0; rp < 2; rp++) {
                    int l = lt*128 + wm*32 + mi*16 + lr + rp*8;
                    unsigned short sp[2];
                    #pragma unroll
                    for (int c = 0; c < 2; c++) {
                        int r = rp*2 + c;
                        float x = acc[mi][ni][r] * 0.125f;
                        float v = vmem[mi][ni][r];
                        float hh = v + (x - v) * 0.5f;
                        bool s = (hh - 0.5f) >= 0.f;
                        sp[c] = s ? 0x3C00 : 0;
                        vmem[mi][ni][r] = s ? 0.f : hh;
                    }
                    *(uint32_t*)(g_s2 + (((size_t)t * Ll + l) * Bb + b) * Ee
                                 + h * 64 + e) = *(uint32_t*)sp;
                }
            }
        }
    }
}

// ---------------------------------------------------------------------------
// GEMM5: out = s2 @ W_out^T + bias, single fp16 pass, BK=64 stages.
// ---------------------------------------------------------------------------
__global__ __launch_bounds__(256) void gemm5_mma_kernel(
    const float* __restrict__ bias, float* __restrict__ C)
{
    extern __shared__ __half dsm[];
    __half* As  = dsm;              // [2][128][72]
    __half* Bhi = dsm + 2*STG64;

    const int bm = blockIdx.y * 128;
    const int bn = blockIdx.x * 128;
    const int tid  = threadIdx.x;
    const int wid  = tid >> 5;
    const int lane = tid & 31;
    const int wm = wid >> 1;
    const int wn = wid & 1;
    const int lr = lane >> 2;
    const int lc = (lane & 3) * 2;

    const int a_r = lane & 15, a_k = (lane >> 4) * 8;
    const int b_r = (lane & 7) + ((lane >> 4) << 3);
    const int b_k = ((lane >> 3) & 1) * 8;

    float acc[2][8][4];
    #pragma unroll
    for (int mi = 0; mi < 2; mi++)
        #pragma unroll
        for (int ni = 0; ni < 8; ni++)
            #pragma unroll
            for (int r = 0; r < 4; r++) acc[mi][ni][r] = 0.f;

    auto load_stage = [&](int s, int k0) {
        #pragma unroll
        for (int i = tid; i < 1024; i += 256) {
            int row = i >> 3, c8 = (i & 7) << 3;
            int so = s*STG64 + row*72 + c8;
            cp16(As + so, g_s2 + (size_t)(bm + row) * Ee + k0 + c8);
            cp16(Bhi + so, g_whi + (size_t)(bn + row) * Ee + k0 + c8);
        }
    };

    load_stage(0, 0);
    CP_COMMIT();

    const int NT = Ee / 64;   // 8
    for (int it = 0; it < NT; it++) {
        if (it + 1 < NT) {
            load_stage((it + 1) & 1, (it + 1) * 64);
            CP_COMMIT();
            CP_WAIT1();
        } else {
            CP_WAIT0();
        }
        __syncthreads();

        const int sb = (it & 1) * STG64;
        #pragma unroll
        for (int kk = 0; kk < 64; kk += 16) {
            uint32_t a[2][4];
            #pragma unroll
            for (int mi = 0; mi < 2; mi++) {
                int rb = wm*32 + mi*16;
                ldsm_x4(a[mi][0], a[mi][1], a[mi][2], a[mi][3],
                        As + sb + (rb + a_r)*72 + kk + a_k);
            }
            uint32_t bh[8][2];
            #pragma unroll
            for (int nb = 0; nb < 4; nb++) {
                int n0 = wn*64 + nb*16;
                ldsm_x4(bh[nb*2][0], bh[nb*2][1], bh[nb*2+1][0], bh[nb*2+1][1],
                        Bhi + sb + (n0 + b_r)*72 + kk + b_k);
            }
            #pragma unroll
            for (int ni = 0; ni < 8; ni++) {
                #pragma unroll
                for (int mi = 0; mi < 2; mi++) {
                    MMA_F16(acc[mi][ni], a[mi][0], a[mi][1], a[mi][2], a[mi][3],
                            bh[ni][0], bh[ni][1]);
                }
            }
        }
        __syncthreads();
    }

    #pragma unroll
    for (int mi = 0; mi < 2; mi++) {
        #pragma unroll
        for (int ni = 0; ni < 8; ni++) {
            int col = bn + wn*64 + ni*8 + lc;
            float b0 = bias[col], b1 = bias[col + 1];
            int row0 = bm + wm*32 + mi*16 + lr;
            *(float2*)(C + (size_t)row0 * Ee + col) =
                make_float2(acc[mi][ni][0] + b0, acc[mi][ni][1] + b1);
            *(float2*)(C + (size_t)(row0 + 8) * Ee + col) =
                make_float2(acc[mi][ni][2] + b0, acc[mi][ni][3] + b1);
        }
    }
}

// ---------------------------------------------------------------------------
extern "C" void kernel_launch(void* const* d_in, const int* in_sizes, int n_in,
                              void* d_out, int out_size)
{
    const float* query = (const float*)d_in[0];   // (T,L,B,E)
    const float* w_in  = (const float*)d_in[1];   // (3E, E)
    const float* b_in  = (const float*)d_in[2];   // (3E)
    const float* w_out = (const float*)d_in[3];   // (E, E)
    const float* b_out = (const float*)d_in[4];   // (E)
    float* out = (float*)d_out;                   // (T,L,B,E)

    void *p_a0, *p_w0, *p_whi;
    cudaGetSymbolAddress(&p_a0, g_a0);
    cudaGetSymbolAddress(&p_w0, g_w0);
    cudaGetSymbolAddress(&p_whi, g_whi);

    // 0) zero flag counter + fp16 converts
    zero_flag_kernel<<<1, 1>>>();
    conv_kernel<<<((size_t)Mm * Ee / 4) / 256, 256>>>(query, (__half*)p_a0);
    conv_kernel<<<((size_t)N3 * Ee / 4) / 256, 256>>>(w_in, (__half*)p_w0);
    conv_kernel<<<((size_t)Ee * Ee / 4) / 256, 256>>>(w_out, (__half*)p_whi);

    // 1) fused proj + LIF + flag on tensor cores (BK=64 stages)
    const int SM1 = 4 * STG64 * (int)sizeof(__half);   // 72 KB (>= 66 KB vsm)
    cudaFuncSetAttribute(gemm1_lif_kernel,
                         cudaFuncAttributeMaxDynamicSharedMemorySize, SM1);
    gemm1_lif_kernel<<<dim3(N3 / 128, LB / 32), 256, SM1>>>(b_in);

    // 2) exact fixup of flagged neurons
    fixup_kernel<<<FIX_CAP / 32, 256>>>(query, w_in, b_in);

    // 3) attnT = v^T k per (t, head) on tensor cores
    kv_attn_kernel<<<dim3(64, Tt), 256>>>();

    // 4) out = q @ attn * 0.125 -> LIF(0.5) -> s2 spikes, tensor cores
    qattn_lif_kernel<<<dim3(Ll / 128, 64), 256>>>();

    // 5) final = s2 @ W_out^T + b_out, single fp16 pass (BK=64 stages)
    const int SM5 = 4 * STG64 * (int)sizeof(__half);   // 72 KB
    cudaFuncSetAttribute(gemm5_mma_kernel,
                         cudaFuncAttributeMaxDynamicSharedMemorySize, SM5);
    gemm5_mma_kernel<<<dim3(Ee / 128, Mm / 128), 256, SM5>>>(b_out, out);
}